// round 14
// baseline (speedup 1.0000x reference)
#include <cuda_runtime.h>
#include <cuda_bf16.h>
#include <math.h>

#define TT 256
#define DD 2048
#define NH 16
#define HDIM 128
#define NE 64
#define TOPK 8
#define DFF 1024
#define EPSF 1e-5f
#define ASCALE 0.08838834764831845f
#define NEGINF -3.4028234663852886e38f

#define LW 24
#define LWB 48

// v13 MoE dynamic smem layout (bytes):
//  A: [stage(2)][plane(2)][32 rows][48B]   -> off 0,     plane 1536, stage 3072, total 6144
//  B: [stage(2)][plane(2)][256 rows][48B]  -> off 6144,  plane 12288, stage 24576, total 49152
#define V13_A_OFF(st, pl)  ((st) * 3072 + (pl) * 1536)
#define V13_B_OFF(st, pl)  (6144 + (st) * 24576 + (pl) * 12288)
#define V13_DSMEM 55296

// ---------------- scratch ----------------
__device__ float g_xn[TT*DD];
__device__ float g_qb[TT*DD];
__device__ float g_kb[TT*DD];
__device__ float g_vb[TT*DD];
__device__ float g_sc[NH*TT*TT];
__device__ float g_ctx[TT*DD];
__device__ float g_x2[TT*DD];
__device__ float g_x3[TT*DD];
__device__ float g_act[(size_t)NE*256*DFF];
__device__ float g_part[(size_t)NE*256*DD];
__device__ int   g_cnt[NE];
__device__ int   g_tok[NE*256];
__device__ float g_wgt[NE*256];
__device__ int   g_inv[TT*TOPK];

// ==================== PTX helpers ====================
__device__ __forceinline__ unsigned smem_u32(const void* p) {
    return (unsigned)__cvta_generic_to_shared(p);
}
__device__ __forceinline__ void ldmat_x4(unsigned addr, unsigned &r0, unsigned &r1,
                                         unsigned &r2, unsigned &r3) {
    asm volatile("ldmatrix.sync.aligned.m8n8.x4.shared.b16 {%0,%1,%2,%3}, [%4];"
        : "=r"(r0), "=r"(r1), "=r"(r2), "=r"(r3) : "r"(addr));
}
__device__ __forceinline__ void mma_bf16(float* c,
    unsigned a0, unsigned a1, unsigned a2, unsigned a3, unsigned b0, unsigned b1) {
    asm volatile("mma.sync.aligned.m16n8k16.row.col.f32.bf16.bf16.f32 "
        "{%0,%1,%2,%3}, {%4,%5,%6,%7}, {%8,%9}, {%0,%1,%2,%3};"
        : "+f"(c[0]), "+f"(c[1]), "+f"(c[2]), "+f"(c[3])
        : "r"(a0), "r"(a1), "r"(a2), "r"(a3), "r"(b0), "r"(b1));
}
__device__ __forceinline__ void split_pair(float x0, float x1, unsigned &h, unsigned &l) {
    asm("cvt.rn.bf16x2.f32 %0, %1, %2;" : "=r"(h) : "f"(x1), "f"(x0));
    float h0 = __uint_as_float(h << 16);
    float h1 = __uint_as_float(h & 0xffff0000u);
    float r0 = x0 - h0, r1 = x1 - h1;
    asm("cvt.rn.bf16x2.f32 %0, %1, %2;" : "=r"(l) : "f"(r1), "f"(r0));
}
__device__ __forceinline__ void cvt_store(float4 v, __nv_bfloat16* ph, __nv_bfloat16* pl) {
    unsigned h0, l0, h1, l1;
    split_pair(v.x, v.y, h0, l0);
    split_pair(v.z, v.w, h1, l1);
    *(uint2*)ph = make_uint2(h0, h1);
    *(uint2*)pl = make_uint2(l0, l1);
}

// ==================== elementwise ====================
__global__ void rms_kernel(const float* __restrict__ in, const float* __restrict__ w,
                           float* __restrict__ out)
{
    int row = blockIdx.x;
    const float* xr = in + (size_t)row * DD;
    float ss = 0.f;
    for (int i = threadIdx.x; i < DD; i += 256) { float v = xr[i]; ss += v * v; }
    __shared__ float red[256];
    red[threadIdx.x] = ss; __syncthreads();
    for (int s = 128; s > 0; s >>= 1) {
        if (threadIdx.x < s) red[threadIdx.x] += red[threadIdx.x + s];
        __syncthreads();
    }
    float r = rsqrtf(red[0] / (float)DD + EPSF);
    for (int i = threadIdx.x; i < DD; i += 256)
        out[(size_t)row * DD + i] = xr[i] * r * w[i];
}

__global__ void qk_norm_rope(float* __restrict__ q, float* __restrict__ k,
                             const float* __restrict__ qn_w, const float* __restrict__ kn_w)
{
    int t = blockIdx.x;
    float* qr = q + (size_t)t * DD;
    float* kr = k + (size_t)t * DD;
    int tid = threadIdx.x;
    float sq = 0.f, sk = 0.f;
    for (int i = tid; i < DD; i += 256) {
        float a = qr[i]; sq += a * a;
        float b = kr[i]; sk += b * b;
    }
    __shared__ float rq_s[256], rk_s[256];
    rq_s[tid] = sq; rk_s[tid] = sk; __syncthreads();
    for (int s = 128; s > 0; s >>= 1) {
        if (tid < s) { rq_s[tid] += rq_s[tid + s]; rk_s[tid] += rk_s[tid + s]; }
        __syncthreads();
    }
    float rq = rsqrtf(rq_s[0] / (float)DD + EPSF);
    float rk = rsqrtf(rk_s[0] / (float)DD + EPSF);
    for (int p = tid; p < NH * 64; p += 256) {
        int h = p >> 6, i = p & 63;
        float inv = __expf(-((float)i / 64.0f) * 9.210340371976184f);
        float ang = (float)t * inv;
        float c = cosf(ang), s = sinf(ang);
        int base = h * HDIM;
        float q1 = qr[base + i]      * rq * qn_w[base + i];
        float q2 = qr[base + 64 + i] * rq * qn_w[base + 64 + i];
        qr[base + i]      = q1 * c - q2 * s;
        qr[base + 64 + i] = q1 * s + q2 * c;
        float k1 = kr[base + i]      * rk * kn_w[base + i];
        float k2 = kr[base + 64 + i] * rk * kn_w[base + 64 + i];
        kr[base + i]      = k1 * c - k2 * s;
        kr[base + 64 + i] = k1 * s + k2 * c;
    }
}

__global__ void softmax_kernel(float* __restrict__ s)
{
    int row = blockIdx.x;
    float* p = s + (size_t)row * TT;
    int i = threadIdx.x;
    float v = p[i];
    __shared__ float red[256];
    red[i] = v; __syncthreads();
    for (int st = 128; st > 0; st >>= 1) {
        if (i < st) red[i] = fmaxf(red[i], red[i + st]);
        __syncthreads();
    }
    float m = red[0]; __syncthreads();
    float e = expf(v - m);
    red[i] = e; __syncthreads();
    for (int st = 128; st > 0; st >>= 1) {
        if (i < st) red[i] += red[i + st];
        __syncthreads();
    }
    p[i] = e / red[0];
}

__global__ void zero_cnt_kernel(int* cnt)
{
    if (threadIdx.x < NE) cnt[threadIdx.x] = 0;
}

__global__ void router_kernel(const float* __restrict__ x3, const float* __restrict__ gw,
                              int* __restrict__ cnt, int* __restrict__ tok,
                              float* __restrict__ wgt, int* __restrict__ inv)
{
    int t = blockIdx.x;
    __shared__ float xr[DD];
    __shared__ float lg[NE];
    for (int i = threadIdx.x; i < DD; i += blockDim.x) xr[i] = x3[(size_t)t * DD + i];
    __syncthreads();
    {
        // 4 threads per expert, 512 elements each, shfl-reduce within quad
        int e = threadIdx.x >> 2, p4 = threadIdx.x & 3;
        const float* wrow = gw + (size_t)e * DD + p4 * 512;
        const float* xp = xr + p4 * 512;
        float acc = 0.f;
        for (int j = 0; j < 512; j++) acc += xp[j] * wrow[j];
        acc += __shfl_down_sync(0xffffffffu, acc, 1, 4);
        acc += __shfl_down_sync(0xffffffffu, acc, 2, 4);
        if (p4 == 0) lg[e] = acc;
    }
    __syncthreads();
    if (threadIdx.x == 0) {
        float mx = -1e30f;
        for (int e = 0; e < NE; e++) mx = fmaxf(mx, lg[e]);
        float sum = 0.f;
        for (int e = 0; e < NE; e++) { lg[e] = expf(lg[e] - mx); sum += lg[e]; }
        bool used[NE];
        for (int e = 0; e < NE; e++) used[e] = false;
        for (int s = 0; s < TOPK; s++) {
            int bi = 0; float bv = -1.f;
            for (int e = 0; e < NE; e++)
                if (!used[e] && lg[e] > bv) { bv = lg[e]; bi = e; }
            used[bi] = true;
            int pos = atomicAdd(&cnt[bi], 1);
            tok[bi * 256 + pos] = t;
            wgt[bi * 256 + pos] = bv / sum;
            inv[t * TOPK + s] = bi * 256 + pos;
        }
    }
}

__global__ void gather_kernel(const float* __restrict__ part, const int* __restrict__ inv,
                              float* __restrict__ out)
{
    int t = blockIdx.x;
    __shared__ int iv[TOPK];
    if (threadIdx.x < TOPK) iv[threadIdx.x] = inv[t * TOPK + threadIdx.x];
    __syncthreads();
    int d = threadIdx.x * 8;
    float4 v0 = *(const float4*)&out[(size_t)t * DD + d];
    float4 v1 = *(const float4*)&out[(size_t)t * DD + d + 4];
#pragma unroll
    for (int s = 0; s < TOPK; s++) {
        const float* p = part + (size_t)iv[s] * DD + d;
        float4 p0 = *(const float4*)p;
        float4 p1 = *(const float4*)(p + 4);
        v0.x += p0.x; v0.y += p0.y; v0.z += p0.z; v0.w += p0.w;
        v1.x += p1.x; v1.y += p1.y; v1.z += p1.z; v1.w += p1.w;
    }
    *(float4*)&out[(size_t)t * DD + d]     = v0;
    *(float4*)&out[(size_t)t * DD + d + 4] = v1;
}

// ==================== attention SIMT GEMMs (proven) ====================
__global__ void score_gemm(const float* __restrict__ Q, const float* __restrict__ Kk,
                           float* __restrict__ S)
{
    int h = blockIdx.z;
    const float* A = Q + h * HDIM;
    const float* B = Kk + h * HDIM;
    float* C = S + (size_t)h * TT * TT;
    __shared__ float As[16][64];
    __shared__ float Bs[16][64];
    int bm = blockIdx.y * 64, bn = blockIdx.x * 64;
    int tid = threadIdx.x;
    int lr = tid >> 2, lc = tid & 3;
    int ty = tid >> 4, tx = tid & 15;
    float acc[4][4];
#pragma unroll
    for (int i = 0; i < 4; i++)
#pragma unroll
        for (int j = 0; j < 4; j++) acc[i][j] = 0.f;
    for (int k0 = 0; k0 < HDIM; k0 += 16) {
        float4 a4 = *(const float4*)(A + (size_t)(bm + lr) * DD + k0 + lc * 4);
        float4 b4 = *(const float4*)(B + (size_t)(bn + lr) * DD + k0 + lc * 4);
        As[lc*4+0][lr] = a4.x; As[lc*4+1][lr] = a4.y; As[lc*4+2][lr] = a4.z; As[lc*4+3][lr] = a4.w;
        Bs[lc*4+0][lr] = b4.x; Bs[lc*4+1][lr] = b4.y; Bs[lc*4+2][lr] = b4.z; Bs[lc*4+3][lr] = b4.w;
        __syncthreads();
#pragma unroll
        for (int kk = 0; kk < 16; kk++) {
            float4 av = *(const float4*)&As[kk][ty*4];
            float4 bv = *(const float4*)&Bs[kk][tx*4];
            float ar[4] = {av.x, av.y, av.z, av.w};
            float br[4] = {bv.x, bv.y, bv.z, bv.w};
#pragma unroll
            for (int i = 0; i < 4; i++)
#pragma unroll
                for (int j = 0; j < 4; j++) acc[i][j] += ar[i] * br[j];
        }
        __syncthreads();
    }
#pragma unroll
    for (int i = 0; i < 4; i++) {
        int row = bm + ty*4 + i;
#pragma unroll
        for (int j = 0; j < 4; j++) {
            int col = bn + tx*4 + j;
            float v = acc[i][j] * ASCALE;
            if (col > row) v = NEGINF;
            C[(size_t)row * TT + col] = v;
        }
    }
}

__global__ void pv_gemm(const float* __restrict__ P, const float* __restrict__ V,
                        float* __restrict__ CTX)
{
    int h = blockIdx.z;
    const float* A = P + (size_t)h * TT * TT;
    const float* B = V + h * HDIM;
    float* C = CTX + h * HDIM;
    __shared__ float As[16][64];
    __shared__ float Bs[16][64];
    int bm = blockIdx.y * 64, bn = blockIdx.x * 64;
    int tid = threadIdx.x;
    int lr = tid >> 2, lc = tid & 3;
    int ty = tid >> 4, tx = tid & 15;
    float acc[4][4];
#pragma unroll
    for (int i = 0; i < 4; i++)
#pragma unroll
        for (int j = 0; j < 4; j++) acc[i][j] = 0.f;
    for (int k0 = 0; k0 < TT; k0 += 16) {
        float4 a4 = *(const float4*)(A + (size_t)(bm + lr) * TT + k0 + lc * 4);
        As[lc*4+0][lr] = a4.x; As[lc*4+1][lr] = a4.y; As[lc*4+2][lr] = a4.z; As[lc*4+3][lr] = a4.w;
#pragma unroll
        for (int i = 0; i < 4; i++) {
            int kr = i * 4 + (tid >> 6);
            Bs[kr][tid & 63] = B[(size_t)(k0 + kr) * DD + bn + (tid & 63)];
        }
        __syncthreads();
#pragma unroll
        for (int kk = 0; kk < 16; kk++) {
            float4 av = *(const float4*)&As[kk][ty*4];
            float4 bv = *(const float4*)&Bs[kk][tx*4];
            float ar[4] = {av.x, av.y, av.z, av.w};
            float br[4] = {bv.x, bv.y, bv.z, bv.w};
#pragma unroll
            for (int i = 0; i < 4; i++)
#pragma unroll
                for (int j = 0; j < 4; j++) acc[i][j] += ar[i] * br[j];
        }
        __syncthreads();
    }
#pragma unroll
    for (int i = 0; i < 4; i++) {
        int row = bm + ty*4 + i;
#pragma unroll
        for (int j = 0; j < 4; j++)
            C[(size_t)row * DD + bn + tx*4 + j] = acc[i][j];
    }
}

// ==================== templated bf16x3 dense NT GEMM ====================
template<int BN>
__device__ __forceinline__ void dense_core(
    const float* __restrict__ A, const float* __restrict__ B,
    float* __restrict__ C, const float* __restrict__ res, float* __restrict__ C2)
{
    constexpr int NFRAG = BN / 16;
    constexpr int BF    = BN / 64;
    __shared__ __align__(16) __nv_bfloat16 sA[2][2][64][LW];
    __shared__ __align__(16) __nv_bfloat16 sB[2][2][BN][LW];
    const int tid = threadIdx.x;
    const int lane = tid & 31, wid = tid >> 5;
    const int wm = wid & 3, wn = wid >> 2;
    const int gid = lane >> 2, tig = lane & 3;
    const int bm = blockIdx.y * 64, bn = blockIdx.x * BN;

    const int ar = tid >> 2, aq = tid & 3;
    const float* gA = A + (size_t)(bm + ar) * DD + aq * 4;
    const float* gB[BF];
#pragma unroll
    for (int i = 0; i < BF; i++)
        gB[i] = B + (size_t)(bn + ar + i * 64) * DD + aq * 4;

    const unsigned baseAh = smem_u32(&sA[0][0][0][0]);
    const unsigned baseAl = smem_u32(&sA[0][1][0][0]);
    const unsigned baseBh = smem_u32(&sB[0][0][0][0]);
    const unsigned baseBl = smem_u32(&sB[0][1][0][0]);
    const unsigned stageA = 2u * 64 * LWB;
    const unsigned stageB = 2u * BN * LWB;
    const int aRow = wm * 16 + (lane & 15);
    const int aColB = ((lane >> 4) & 1) * 16;
    const unsigned aOffH = baseAh + aRow * LWB + aColB;
    const unsigned aOffL = baseAl + aRow * LWB + aColB;
    const int bRow = wn * (BN / 2) + (lane & 7) + ((lane >> 4) & 1) * 8;
    const int bColB = ((lane >> 3) & 1) * 16;
    const unsigned bOffH = baseBh + bRow * LWB + bColB;
    const unsigned bOffL = baseBl + bRow * LWB + bColB;

    float acc[NFRAG][4];
#pragma unroll
    for (int t = 0; t < NFRAG; t++)
#pragma unroll
        for (int j = 0; j < 4; j++) acc[t][j] = 0.f;

    float4 a4, b4[BF];
    a4 = *(const float4*)gA;
#pragma unroll
    for (int i = 0; i < BF; i++) b4[i] = *(const float4*)gB[i];
    cvt_store(a4, &sA[0][0][ar][aq*4], &sA[0][1][ar][aq*4]);
#pragma unroll
    for (int i = 0; i < BF; i++)
        cvt_store(b4[i], &sB[0][0][ar + i*64][aq*4], &sB[0][1][ar + i*64][aq*4]);
    __syncthreads();

    const int NIT = DD / 16;
    for (int it = 0; it < NIT; it++) {
        const int cur = it & 1;
        const bool nx = (it + 1 < NIT);
        if (nx) {
            const int k0 = (it + 1) * 16;
            a4 = *(const float4*)(gA + k0);
#pragma unroll
            for (int i = 0; i < BF; i++) b4[i] = *(const float4*)(gB[i] + k0);
        }
        const unsigned soA = cur * stageA;
        const unsigned soB = cur * stageB;
        unsigned ah0,ah1,ah2,ah3, al0,al1,al2,al3;
        ldmat_x4(aOffH + soA, ah0, ah1, ah2, ah3);
        ldmat_x4(aOffL + soA, al0, al1, al2, al3);
#pragma unroll
        for (int p = 0; p < BN / 32; p++) {
            unsigned bh0,bh1,bh2,bh3, bl0,bl1,bl2,bl3;
            ldmat_x4(bOffH + soB + p * 16 * LWB, bh0, bh1, bh2, bh3);
            ldmat_x4(bOffL + soB + p * 16 * LWB, bl0, bl1, bl2, bl3);
            mma_bf16(acc[2*p],   ah0,ah1,ah2,ah3, bh0,bh1);
            mma_bf16(acc[2*p+1], ah0,ah1,ah2,ah3, bh2,bh3);
            mma_bf16(acc[2*p],   ah0,ah1,ah2,ah3, bl0,bl1);
            mma_bf16(acc[2*p+1], ah0,ah1,ah2,ah3, bl2,bl3);
            mma_bf16(acc[2*p],   al0,al1,al2,al3, bh0,bh1);
            mma_bf16(acc[2*p+1], al0,al1,al2,al3, bh2,bh3);
        }
        if (nx) {
            const int ns = cur ^ 1;
            cvt_store(a4, &sA[ns][0][ar][aq*4], &sA[ns][1][ar][aq*4]);
#pragma unroll
            for (int i = 0; i < BF; i++)
                cvt_store(b4[i], &sB[ns][0][ar + i*64][aq*4], &sB[ns][1][ar + i*64][aq*4]);
        }
        __syncthreads();
    }

#pragma unroll
    for (int t = 0; t < NFRAG; t++) {
        const int col = bn + wn * (BN / 2) + t * 8 + tig * 2;
        const int r0 = bm + wm * 16 + gid, r1 = r0 + 8;
        float2 v0 = make_float2(acc[t][0], acc[t][1]);
        float2 v1 = make_float2(acc[t][2], acc[t][3]);
        if (res) {
            float2 e0 = *(const float2*)&res[(size_t)r0 * DD + col];
            float2 e1 = *(const float2*)&res[(size_t)r1 * DD + col];
            v0.x += e0.x; v0.y += e0.y; v1.x += e1.x; v1.y += e1.y;
        }
        *(float2*)&C[(size_t)r0 * DD + col] = v0;
        *(float2*)&C[(size_t)r1 * DD + col] = v1;
        if (C2) {
            *(float2*)&C2[(size_t)r0 * DD + col] = v0;
            *(float2*)&C2[(size_t)r1 * DD + col] = v1;
        }
    }
}

__global__ void qkv_tc_kernel(const float* __restrict__ xn,
                              const float* __restrict__ qw, const float* __restrict__ kw,
                              const float* __restrict__ vw,
                              float* __restrict__ qb, float* __restrict__ kb,
                              float* __restrict__ vb)
{
    const float* B; float* C;
    if (blockIdx.z == 0)      { B = qw; C = qb; }
    else if (blockIdx.z == 1) { B = kw; C = kb; }
    else                      { B = vw; C = vb; }
    dense_core<64>(xn, B, C, nullptr, nullptr);
}

__global__ void oproj_tc_kernel(const float* __restrict__ ctx, const float* __restrict__ ow,
                                const float* __restrict__ x, float* __restrict__ x2,
                                float* __restrict__ out)
{
    dense_core<64>(ctx, ow, x2, x, out);
}

// ==================== v13 MoE core: 32 tokens x 256 B-rows, warp tile 32x32 ====================
// Warp w owns B rows [w*32, w*32+32) exclusively. A (32 rows) shared by all warps.
// Fragment loop body shared via macro; epilogue differs per kernel.

#define V13_FRAG_SETUP() \
    const unsigned sbase = smem_u32(dsm); \
    const unsigned aOffH0 = sbase + V13_A_OFF(0,0) + ((lane & 15)     ) * LWB + ((lane >> 4) & 1) * 16; \
    const unsigned aOffH1 = aOffH0 + 16 * LWB; \
    const unsigned aOffL0 = aOffH0 + 1536; \
    const unsigned aOffL1 = aOffH1 + 1536; \
    const unsigned bOffH  = sbase + V13_B_OFF(0,0) + (wid * 32 + (lane & 7) + ((lane >> 4) & 1) * 8) * LWB \
                            + ((lane >> 3) & 1) * 16; \
    const unsigned bOffL  = bOffH + 12288;

#define V13_COMPUTE(cur) do { \
    const unsigned soA = (cur) * 3072; \
    const unsigned soB = (cur) * 24576; \
    unsigned ah[2][4], al[2][4]; \
    ldmat_x4(aOffH0 + soA, ah[0][0], ah[0][1], ah[0][2], ah[0][3]); \
    ldmat_x4(aOffH1 + soA, ah[1][0], ah[1][1], ah[1][2], ah[1][3]); \
    ldmat_x4(aOffL0 + soA, al[0][0], al[0][1], al[0][2], al[0][3]); \
    ldmat_x4(aOffL1 + soA, al[1][0], al[1][1], al[1][2], al[1][3]); \
    _Pragma("unroll") \
    for (int p = 0; p < 2; p++) { \
        unsigned bh0,bh1,bh2,bh3, bl0,bl1,bl2,bl3; \
        ldmat_x4(bOffH + soB + p * 16 * LWB, bh0, bh1, bh2, bh3); \
        ldmat_x4(bOffL + soB + p * 16 * LWB, bl0, bl1, bl2, bl3); \
        _Pragma("unroll") \
        for (int mf = 0; mf < 2; mf++) { \
            float* c0 = acc[mf*4 + p*2 + 0]; \
            float* c1 = acc[mf*4 + p*2 + 1]; \
            mma_bf16(c0, ah[mf][0],ah[mf][1],ah[mf][2],ah[mf][3], bh0, bh1); \
            mma_bf16(c1, ah[mf][0],ah[mf][1],ah[mf][2],ah[mf][3], bh2, bh3); \
            mma_bf16(c0, ah[mf][0],ah[mf][1],ah[mf][2],ah[mf][3], bl0, bl1); \
            mma_bf16(c1, ah[mf][0],ah[mf][1],ah[mf][2],ah[mf][3], bl2, bl3); \
            mma_bf16(c0, al[mf][0],al[mf][1],al[mf][2],al[mf][3], bh0, bh1); \
            mma_bf16(c1, al[mf][0],al[mf][1],al[mf][2],al[mf][3], bh2, bh3); \
        } \
    } \
} while (0)

#define V13_LOAD(k0) do { \
    if (tid < 128) a4 = *(const float4*)(gA + (k0)); \
    _Pragma("unroll") for (int f = 0; f < 4; f++) b4[f] = *(const float4*)(bP[f] + (k0)); \
} while (0)

#define V13_STORE(st) do { \
    if (tid < 128) \
        cvt_store(a4, (__nv_bfloat16*)(dsm + V13_A_OFF(st,0) + ar * LWB) + aq * 4, \
                      (__nv_bfloat16*)(dsm + V13_A_OFF(st,1) + ar * LWB) + aq * 4); \
    _Pragma("unroll") for (int f = 0; f < 4; f++) { \
        int idx = tid + f * 256; int br_ = idx >> 2, bq_ = idx & 3; \
        cvt_store(b4[f], (__nv_bfloat16*)(dsm + V13_B_OFF(st,0) + br_ * LWB) + bq_ * 4, \
                         (__nv_bfloat16*)(dsm + V13_B_OFF(st,1) + br_ * LWB) + bq_ * 4); } \
} while (0)

// ---- gate_up: CTA = 32 tokens x 128 cols (gate rows 0-127, up rows 128-255 in B smem) ----
__global__ __launch_bounds__(256, 2)
void moe_gate_up_v13(const float* __restrict__ x3, const float* __restrict__ w_gu,
                     const int* __restrict__ cnt, const int* __restrict__ tok,
                     const float* __restrict__ wgt, float* __restrict__ act)
{
    extern __shared__ __align__(16) char dsm[];
    const int e = blockIdx.z;
    const int nt = cnt[e];
    const int m0 = blockIdx.y * 32;
    if (m0 >= nt) return;
    const int n0 = blockIdx.x * 128;
    const int tid = threadIdx.x, lane = tid & 31, wid = tid >> 5;
    const int gid = lane >> 2, tig = lane & 3;
    float* Cs = (float*)(dsm + 6144);   // 32 x 260 fp32 = 33280B, aliases sB after final sync

    __shared__ int   stok[32];
    __shared__ float sw_[32];
    if (tid < 32) {
        int rr = min(m0 + tid, nt - 1);
        stok[tid] = tok[e * 256 + rr];
        sw_[tid]  = wgt[e * 256 + rr];
    }
    __syncthreads();

    const int ar = tid >> 2, aq = tid & 3;
    const float* gA = x3 + (size_t)stok[(tid < 128) ? ar : 0] * DD + aq * 4;
    const float* Wg = w_gu + (size_t)e * (2 * DFF) * DD;
    const float* bP[4];
#pragma unroll
    for (int f = 0; f < 4; f++) {
        int idx = tid + f * 256; int r = idx >> 2, q = idx & 3;
        bP[f] = ((r < 128) ? (Wg + (size_t)(n0 + r) * DD)
                           : (Wg + (size_t)(DFF + n0 + r - 128) * DD)) + q * 4;
    }

    V13_FRAG_SETUP();

    float acc[8][4];
#pragma unroll
    for (int t = 0; t < 8; t++)
#pragma unroll
        for (int j = 0; j < 4; j++) acc[t][j] = 0.f;

    float4 a4 = make_float4(0.f,0.f,0.f,0.f), b4[4];
    V13_LOAD(0);
    V13_STORE(0);
    __syncthreads();

    const int NIT = DD / 16;
    for (int it = 0; it < NIT; it++) {
        const int cur = it & 1;
        const bool nx = (it + 1 < NIT);
        if (nx) V13_LOAD((it + 1) * 16);
        V13_COMPUTE(cur);
        if (nx) V13_STORE(cur ^ 1);
        __syncthreads();
    }

    // stage accs: Cs cols 0..127 gate (warps 0-3), 128..255 up (warps 4-7)
#pragma unroll
    for (int mf = 0; mf < 2; mf++)
#pragma unroll
        for (int p = 0; p < 2; p++)
#pragma unroll
            for (int jj = 0; jj < 2; jj++) {
                float* c = acc[mf*4 + p*2 + jj];
                const int row = mf * 16 + gid;
                const int col = wid * 32 + p * 16 + jj * 8 + tig * 2;
                Cs[row * 260 + col]       = c[0];
                Cs[row * 260 + col + 1]   = c[1];
                Cs[(row+8) * 260 + col]   = c[2];
                Cs[(row+8) * 260 + col+1] = c[3];
            }
    __syncthreads();

    const int m = tid >> 3;
    if (m0 + m < nt) {
        const float w = sw_[m];
        const int j0 = (tid & 7) * 16;
        const size_t base = ((size_t)(e * 256 + m0 + m)) * DFF + n0 + j0;
#pragma unroll
        for (int j = 0; j < 16; j++) {
            float g = Cs[m * 260 + j0 + j];
            float u = Cs[m * 260 + 128 + j0 + j];
            float sg = g / (1.f + expf(-g));
            act[base + j] = sg * u * w;
        }
    }
}

// ---- down: CTA = 32 tokens x 256 out cols; plain stores to part ----
__global__ __launch_bounds__(256, 2)
void moe_down_v13(const float* __restrict__ act, const float* __restrict__ w_down,
                  const int* __restrict__ cnt, float* __restrict__ part)
{
    extern __shared__ __align__(16) char dsm[];
    const int e = blockIdx.z;
    const int nt = cnt[e];
    const int m0 = blockIdx.y * 32;
    if (m0 >= nt) return;
    const int n0 = blockIdx.x * 256;
    const int tid = threadIdx.x, lane = tid & 31, wid = tid >> 5;
    const int gid = lane >> 2, tig = lane & 3;

    const int ar = tid >> 2, aq = tid & 3;
    // rows >= nt read in-bounds stale data; their partials are never gathered
    const float* gA = act + ((size_t)(e * 256 + m0 + ((tid < 128) ? ar : 0))) * DFF + aq * 4;
    const float* W = w_down + (size_t)e * DD * DFF;
    const float* bP[4];
#pragma unroll
    for (int f = 0; f < 4; f++) {
        int idx = tid + f * 256; int r = idx >> 2, q = idx & 3;
        bP[f] = W + (size_t)(n0 + r) * DFF + q * 4;
    }

    V13_FRAG_SETUP();

    float acc[8][4];
#pragma unroll
    for (int t = 0; t < 8; t++)
#pragma unroll
        for (int j = 0; j < 4; j++) acc[t][j] = 0.f;

    float4 a4 = make_float4(0.f,0.f,0.f,0.f), b4[4];
    V13_LOAD(0);
    V13_STORE(0);
    __syncthreads();

    const int NIT = DFF / 16;
    for (int it = 0; it < NIT; it++) {
        const int cur = it & 1;
        const bool nx = (it + 1 < NIT);
        if (nx) V13_LOAD((it + 1) * 16);
        V13_COMPUTE(cur);
        if (nx) V13_STORE(cur ^ 1);
        __syncthreads();
    }

#pragma unroll
    for (int mf = 0; mf < 2; mf++)
#pragma unroll
        for (int p = 0; p < 2; p++)
#pragma unroll
            for (int jj = 0; jj < 2; jj++) {
                float* c = acc[mf*4 + p*2 + jj];
                const int row = mf * 16 + gid;
                const int col = n0 + wid * 32 + p * 16 + jj * 8 + tig * 2;
                *(float2*)&part[(size_t)(e * 256 + m0 + row) * DD + col]     = make_float2(c[0], c[1]);
                *(float2*)&part[(size_t)(e * 256 + m0 + row + 8) * DD + col] = make_float2(c[2], c[3]);
            }
}

// ==================== host launch ====================
extern "C" void kernel_launch(void* const* d_in, const int* in_sizes, int n_in,
                              void* d_out, int out_size)
{
    const float* x    = (const float*)d_in[0];
    const float* ln1  = (const float*)d_in[1];
    const float* qw   = (const float*)d_in[2];
    const float* kw   = (const float*)d_in[3];
    const float* vw   = (const float*)d_in[4];
    const float* qn   = (const float*)d_in[5];
    const float* kn   = (const float*)d_in[6];
    const float* ow   = (const float*)d_in[7];
    const float* ln2  = (const float*)d_in[8];
    const float* gw   = (const float*)d_in[9];
    const float* guw  = (const float*)d_in[10];
    const float* dw   = (const float*)d_in[11];
    float* out = (float*)d_out;

    float *p_xn, *p_qb, *p_kb, *p_vb, *p_sc, *p_ctx, *p_x2, *p_x3, *p_act, *p_part, *p_wgt;
    int *p_cnt, *p_tok, *p_inv;
    cudaGetSymbolAddress((void**)&p_xn,  g_xn);
    cudaGetSymbolAddress((void**)&p_qb,  g_qb);
    cudaGetSymbolAddress((void**)&p_kb,  g_kb);
    cudaGetSymbolAddress((void**)&p_vb,  g_vb);
    cudaGetSymbolAddress((void**)&p_sc,  g_sc);
    cudaGetSymbolAddress((void**)&p_ctx, g_ctx);
    cudaGetSymbolAddress((void**)&p_x2,  g_x2);
    cudaGetSymbolAddress((void**)&p_x3,  g_x3);
    cudaGetSymbolAddress((void**)&p_act, g_act);
    cudaGetSymbolAddress((void**)&p_part, g_part);
    cudaGetSymbolAddress((void**)&p_cnt, g_cnt);
    cudaGetSymbolAddress((void**)&p_tok, g_tok);
    cudaGetSymbolAddress((void**)&p_wgt, g_wgt);
    cudaGetSymbolAddress((void**)&p_inv, g_inv);

    static int smem_set = 0;
    if (!smem_set) {
        cudaFuncSetAttribute(moe_gate_up_v13, cudaFuncAttributeMaxDynamicSharedMemorySize, V13_DSMEM);
        cudaFuncSetAttribute(moe_down_v13,    cudaFuncAttributeMaxDynamicSharedMemorySize, V13_DSMEM);
        smem_set = 1;
    }

    // #1: xn = rms(x, ln1)
    rms_kernel<<<TT, 256>>>(x, ln1, p_xn);

    // #2: q/k/v projections (BN=64, 384 CTAs)
    dim3 gqkv(DD / 64, TT / 64, 3);
    qkv_tc_kernel<<<gqkv, 256>>>(p_xn, qw, kw, vw, p_qb, p_kb, p_vb);

    // #3: fused q/k RMS + RoPE
    qk_norm_rope<<<TT, 256>>>(p_qb, p_kb, qn, kn);

    // #4: scores + causal
    dim3 gsc(TT / 64, TT / 64, NH);
    score_gemm<<<gsc, 256>>>(p_qb, p_kb, p_sc);

    // #5: softmax
    softmax_kernel<<<NH * TT, 256>>>(p_sc);

    // #6: ctx = P @ V
    dim3 gpv(HDIM / 64, TT / 64, NH);
    pv_gemm<<<gpv, 256>>>(p_sc, p_vb, p_ctx);

    // #7: x2 = x + ctx @ ow^T, dual-store into out
    dim3 go(DD / 64, TT / 64, 1);
    oproj_tc_kernel<<<go, 256>>>(p_ctx, ow, x, p_x2, out);

    // #8: x3 = rms(x2, ln2)
    rms_kernel<<<TT, 256>>>(p_x2, ln2, p_x3);

    // #9-10: router
    zero_cnt_kernel<<<1, 64>>>(p_cnt);
    router_kernel<<<TT, 256>>>(p_x3, gw, p_cnt, p_tok, p_wgt, p_inv);

    // #11: MoE gate_up (v13: 32x256 tile, warp-exclusive B)
    dim3 ggu(DFF / 128, 8, NE);
    moe_gate_up_v13<<<ggu, 256, V13_DSMEM>>>(p_x3, guw, p_cnt, p_tok, p_wgt, p_act);

    // #12: MoE down (v13, no atomics)
    dim3 gdn(DD / 256, 8, NE);
    moe_down_v13<<<gdn, 256, V13_DSMEM>>>(p_act, dw, p_cnt, p_part);

    // #13: gather partials into out
    gather_kernel<<<TT, 256>>>(p_part, p_inv, out);
}

// round 15
// speedup vs baseline: 1.0622x; 1.0622x over previous
#include <cuda_runtime.h>
#include <cuda_bf16.h>
#include <math.h>

#define TT 256
#define DD 2048
#define NH 16
#define HDIM 128
#define NE 64
#define TOPK 8
#define DFF 1024
#define EPSF 1e-5f
#define ASCALE 0.08838834764831845f
#define NEGINF -3.4028234663852886e38f

#define LW 24
#define LWB 48

// v15 MoE smem: BK=32, 80B row stride (64B data + 16B pad), conflict-free, 16B-aligned.
// A: [st2][pl2][32 rows][80B]  plane 2560,  total 10240
// B: [st2][pl2][128 rows][80B] plane 10240, total 40960
#define V15_A_OFF(st, pl)  (((st) * 2 + (pl)) * 2560)
#define V15_B_OFF(st, pl)  (10240 + ((st) * 2 + (pl)) * 10240)
#define V15_DSMEM 51200
#define RS 80

// ---------------- scratch ----------------
__device__ float g_xn[TT*DD];
__device__ float g_qb[TT*DD];
__device__ float g_kb[TT*DD];
__device__ float g_vb[TT*DD];
__device__ float g_sc[NH*TT*TT];
__device__ float g_ctx[TT*DD];
__device__ float g_x2[TT*DD];
__device__ float g_x3[TT*DD];
__device__ float g_act[(size_t)NE*256*DFF];
__device__ float g_part[(size_t)NE*256*DD];
__device__ int   g_cnt[NE];
__device__ int   g_tok[NE*256];
__device__ float g_wgt[NE*256];
__device__ int   g_inv[TT*TOPK];

// ==================== PTX helpers ====================
__device__ __forceinline__ unsigned smem_u32(const void* p) {
    return (unsigned)__cvta_generic_to_shared(p);
}
__device__ __forceinline__ void ldmat_x4(unsigned addr, unsigned &r0, unsigned &r1,
                                         unsigned &r2, unsigned &r3) {
    asm volatile("ldmatrix.sync.aligned.m8n8.x4.shared.b16 {%0,%1,%2,%3}, [%4];"
        : "=r"(r0), "=r"(r1), "=r"(r2), "=r"(r3) : "r"(addr));
}
__device__ __forceinline__ void mma_bf16(float* c,
    unsigned a0, unsigned a1, unsigned a2, unsigned a3, unsigned b0, unsigned b1) {
    asm volatile("mma.sync.aligned.m16n8k16.row.col.f32.bf16.bf16.f32 "
        "{%0,%1,%2,%3}, {%4,%5,%6,%7}, {%8,%9}, {%0,%1,%2,%3};"
        : "+f"(c[0]), "+f"(c[1]), "+f"(c[2]), "+f"(c[3])
        : "r"(a0), "r"(a1), "r"(a2), "r"(a3), "r"(b0), "r"(b1));
}
__device__ __forceinline__ void split_pair(float x0, float x1, unsigned &h, unsigned &l) {
    asm("cvt.rn.bf16x2.f32 %0, %1, %2;" : "=r"(h) : "f"(x1), "f"(x0));
    float h0 = __uint_as_float(h << 16);
    float h1 = __uint_as_float(h & 0xffff0000u);
    float r0 = x0 - h0, r1 = x1 - h1;
    asm("cvt.rn.bf16x2.f32 %0, %1, %2;" : "=r"(l) : "f"(r1), "f"(r0));
}
__device__ __forceinline__ void cvt_store(float4 v, __nv_bfloat16* ph, __nv_bfloat16* pl) {
    unsigned h0, l0, h1, l1;
    split_pair(v.x, v.y, h0, l0);
    split_pair(v.z, v.w, h1, l1);
    *(uint2*)ph = make_uint2(h0, h1);
    *(uint2*)pl = make_uint2(l0, l1);
}

// ==================== elementwise ====================
__global__ void rms_kernel(const float* __restrict__ in, const float* __restrict__ w,
                           float* __restrict__ out)
{
    int row = blockIdx.x;
    const float* xr = in + (size_t)row * DD;
    float ss = 0.f;
    for (int i = threadIdx.x; i < DD; i += 256) { float v = xr[i]; ss += v * v; }
    __shared__ float red[256];
    red[threadIdx.x] = ss; __syncthreads();
    for (int s = 128; s > 0; s >>= 1) {
        if (threadIdx.x < s) red[threadIdx.x] += red[threadIdx.x + s];
        __syncthreads();
    }
    float r = rsqrtf(red[0] / (float)DD + EPSF);
    for (int i = threadIdx.x; i < DD; i += 256)
        out[(size_t)row * DD + i] = xr[i] * r * w[i];
}

__global__ void qk_norm_rope(float* __restrict__ q, float* __restrict__ k,
                             const float* __restrict__ qn_w, const float* __restrict__ kn_w)
{
    int t = blockIdx.x;
    float* qr = q + (size_t)t * DD;
    float* kr = k + (size_t)t * DD;
    int tid = threadIdx.x;
    float sq = 0.f, sk = 0.f;
    for (int i = tid; i < DD; i += 256) {
        float a = qr[i]; sq += a * a;
        float b = kr[i]; sk += b * b;
    }
    __shared__ float rq_s[256], rk_s[256];
    rq_s[tid] = sq; rk_s[tid] = sk; __syncthreads();
    for (int s = 128; s > 0; s >>= 1) {
        if (tid < s) { rq_s[tid] += rq_s[tid + s]; rk_s[tid] += rk_s[tid + s]; }
        __syncthreads();
    }
    float rq = rsqrtf(rq_s[0] / (float)DD + EPSF);
    float rk = rsqrtf(rk_s[0] / (float)DD + EPSF);
    for (int p = tid; p < NH * 64; p += 256) {
        int h = p >> 6, i = p & 63;
        float inv = __expf(-((float)i / 64.0f) * 9.210340371976184f);
        float ang = (float)t * inv;
        float c = cosf(ang), s = sinf(ang);
        int base = h * HDIM;
        float q1 = qr[base + i]      * rq * qn_w[base + i];
        float q2 = qr[base + 64 + i] * rq * qn_w[base + 64 + i];
        qr[base + i]      = q1 * c - q2 * s;
        qr[base + 64 + i] = q1 * s + q2 * c;
        float k1 = kr[base + i]      * rk * kn_w[base + i];
        float k2 = kr[base + 64 + i] * rk * kn_w[base + 64 + i];
        kr[base + i]      = k1 * c - k2 * s;
        kr[base + 64 + i] = k1 * s + k2 * c;
    }
}

__global__ void softmax_kernel(float* __restrict__ s)
{
    int row = blockIdx.x;
    float* p = s + (size_t)row * TT;
    int i = threadIdx.x;
    float v = p[i];
    __shared__ float red[256];
    red[i] = v; __syncthreads();
    for (int st = 128; st > 0; st >>= 1) {
        if (i < st) red[i] = fmaxf(red[i], red[i + st]);
        __syncthreads();
    }
    float m = red[0]; __syncthreads();
    float e = expf(v - m);
    red[i] = e; __syncthreads();
    for (int st = 128; st > 0; st >>= 1) {
        if (i < st) red[i] += red[i + st];
        __syncthreads();
    }
    p[i] = e / red[0];
}

__global__ void zero_cnt_kernel(int* cnt)
{
    if (threadIdx.x < NE) cnt[threadIdx.x] = 0;
}

__global__ void router_kernel(const float* __restrict__ x3, const float* __restrict__ gw,
                              int* __restrict__ cnt, int* __restrict__ tok,
                              float* __restrict__ wgt, int* __restrict__ inv)
{
    int t = blockIdx.x;
    __shared__ float xr[DD];
    __shared__ float lg[NE];
    for (int i = threadIdx.x; i < DD; i += blockDim.x) xr[i] = x3[(size_t)t * DD + i];
    __syncthreads();
    {
        int e = threadIdx.x >> 2, p4 = threadIdx.x & 3;
        const float* wrow = gw + (size_t)e * DD + p4 * 512;
        const float* xp = xr + p4 * 512;
        float acc = 0.f;
        for (int j = 0; j < 512; j++) acc += xp[j] * wrow[j];
        acc += __shfl_down_sync(0xffffffffu, acc, 1, 4);
        acc += __shfl_down_sync(0xffffffffu, acc, 2, 4);
        if (p4 == 0) lg[e] = acc;
    }
    __syncthreads();
    if (threadIdx.x == 0) {
        float mx = -1e30f;
        for (int e = 0; e < NE; e++) mx = fmaxf(mx, lg[e]);
        float sum = 0.f;
        for (int e = 0; e < NE; e++) { lg[e] = expf(lg[e] - mx); sum += lg[e]; }
        bool used[NE];
        for (int e = 0; e < NE; e++) used[e] = false;
        for (int s = 0; s < TOPK; s++) {
            int bi = 0; float bv = -1.f;
            for (int e = 0; e < NE; e++)
                if (!used[e] && lg[e] > bv) { bv = lg[e]; bi = e; }
            used[bi] = true;
            int pos = atomicAdd(&cnt[bi], 1);
            tok[bi * 256 + pos] = t;
            wgt[bi * 256 + pos] = bv / sum;
            inv[t * TOPK + s] = bi * 256 + pos;
        }
    }
}

__global__ void gather_kernel(const float* __restrict__ part, const int* __restrict__ inv,
                              float* __restrict__ out)
{
    int t = blockIdx.x;
    __shared__ int iv[TOPK];
    if (threadIdx.x < TOPK) iv[threadIdx.x] = inv[t * TOPK + threadIdx.x];
    __syncthreads();
    int d = threadIdx.x * 8;
    float4 v0 = *(const float4*)&out[(size_t)t * DD + d];
    float4 v1 = *(const float4*)&out[(size_t)t * DD + d + 4];
#pragma unroll
    for (int s = 0; s < TOPK; s++) {
        const float* p = part + (size_t)iv[s] * DD + d;
        float4 p0 = *(const float4*)p;
        float4 p1 = *(const float4*)(p + 4);
        v0.x += p0.x; v0.y += p0.y; v0.z += p0.z; v0.w += p0.w;
        v1.x += p1.x; v1.y += p1.y; v1.z += p1.z; v1.w += p1.w;
    }
    *(float4*)&out[(size_t)t * DD + d]     = v0;
    *(float4*)&out[(size_t)t * DD + d + 4] = v1;
}

// ==================== attention SIMT GEMMs (proven) ====================
__global__ void score_gemm(const float* __restrict__ Q, const float* __restrict__ Kk,
                           float* __restrict__ S)
{
    int h = blockIdx.z;
    const float* A = Q + h * HDIM;
    const float* B = Kk + h * HDIM;
    float* C = S + (size_t)h * TT * TT;
    __shared__ float As[16][64];
    __shared__ float Bs[16][64];
    int bm = blockIdx.y * 64, bn = blockIdx.x * 64;
    int tid = threadIdx.x;
    int lr = tid >> 2, lc = tid & 3;
    int ty = tid >> 4, tx = tid & 15;
    float acc[4][4];
#pragma unroll
    for (int i = 0; i < 4; i++)
#pragma unroll
        for (int j = 0; j < 4; j++) acc[i][j] = 0.f;
    for (int k0 = 0; k0 < HDIM; k0 += 16) {
        float4 a4 = *(const float4*)(A + (size_t)(bm + lr) * DD + k0 + lc * 4);
        float4 b4 = *(const float4*)(B + (size_t)(bn + lr) * DD + k0 + lc * 4);
        As[lc*4+0][lr] = a4.x; As[lc*4+1][lr] = a4.y; As[lc*4+2][lr] = a4.z; As[lc*4+3][lr] = a4.w;
        Bs[lc*4+0][lr] = b4.x; Bs[lc*4+1][lr] = b4.y; Bs[lc*4+2][lr] = b4.z; Bs[lc*4+3][lr] = b4.w;
        __syncthreads();
#pragma unroll
        for (int kk = 0; kk < 16; kk++) {
            float4 av = *(const float4*)&As[kk][ty*4];
            float4 bv = *(const float4*)&Bs[kk][tx*4];
            float ar[4] = {av.x, av.y, av.z, av.w};
            float br[4] = {bv.x, bv.y, bv.z, bv.w};
#pragma unroll
            for (int i = 0; i < 4; i++)
#pragma unroll
                for (int j = 0; j < 4; j++) acc[i][j] += ar[i] * br[j];
        }
        __syncthreads();
    }
#pragma unroll
    for (int i = 0; i < 4; i++) {
        int row = bm + ty*4 + i;
#pragma unroll
        for (int j = 0; j < 4; j++) {
            int col = bn + tx*4 + j;
            float v = acc[i][j] * ASCALE;
            if (col > row) v = NEGINF;
            C[(size_t)row * TT + col] = v;
        }
    }
}

__global__ void pv_gemm(const float* __restrict__ P, const float* __restrict__ V,
                        float* __restrict__ CTX)
{
    int h = blockIdx.z;
    const float* A = P + (size_t)h * TT * TT;
    const float* B = V + h * HDIM;
    float* C = CTX + h * HDIM;
    __shared__ float As[16][64];
    __shared__ float Bs[16][64];
    int bm = blockIdx.y * 64, bn = blockIdx.x * 64;
    int tid = threadIdx.x;
    int lr = tid >> 2, lc = tid & 3;
    int ty = tid >> 4, tx = tid & 15;
    float acc[4][4];
#pragma unroll
    for (int i = 0; i < 4; i++)
#pragma unroll
        for (int j = 0; j < 4; j++) acc[i][j] = 0.f;
    for (int k0 = 0; k0 < TT; k0 += 16) {
        float4 a4 = *(const float4*)(A + (size_t)(bm + lr) * TT + k0 + lc * 4);
        As[lc*4+0][lr] = a4.x; As[lc*4+1][lr] = a4.y; As[lc*4+2][lr] = a4.z; As[lc*4+3][lr] = a4.w;
#pragma unroll
        for (int i = 0; i < 4; i++) {
            int kr = i * 4 + (tid >> 6);
            Bs[kr][tid & 63] = B[(size_t)(k0 + kr) * DD + bn + (tid & 63)];
        }
        __syncthreads();
#pragma unroll
        for (int kk = 0; kk < 16; kk++) {
            float4 av = *(const float4*)&As[kk][ty*4];
            float4 bv = *(const float4*)&Bs[kk][tx*4];
            float ar[4] = {av.x, av.y, av.z, av.w};
            float br[4] = {bv.x, bv.y, bv.z, bv.w};
#pragma unroll
            for (int i = 0; i < 4; i++)
#pragma unroll
                for (int j = 0; j < 4; j++) acc[i][j] += ar[i] * br[j];
        }
        __syncthreads();
    }
#pragma unroll
    for (int i = 0; i < 4; i++) {
        int row = bm + ty*4 + i;
#pragma unroll
        for (int j = 0; j < 4; j++)
            C[(size_t)row * DD + bn + tx*4 + j] = acc[i][j];
    }
}

// ==================== templated bf16x3 dense NT GEMM ====================
template<int BN>
__device__ __forceinline__ void dense_core(
    const float* __restrict__ A, const float* __restrict__ B,
    float* __restrict__ C, const float* __restrict__ res, float* __restrict__ C2)
{
    constexpr int NFRAG = BN / 16;
    constexpr int BF    = BN / 64;
    __shared__ __align__(16) __nv_bfloat16 sA[2][2][64][LW];
    __shared__ __align__(16) __nv_bfloat16 sB[2][2][BN][LW];
    const int tid = threadIdx.x;
    const int lane = tid & 31, wid = tid >> 5;
    const int wm = wid & 3, wn = wid >> 2;
    const int gid = lane >> 2, tig = lane & 3;
    const int bm = blockIdx.y * 64, bn = blockIdx.x * BN;

    const int ar = tid >> 2, aq = tid & 3;
    const float* gA = A + (size_t)(bm + ar) * DD + aq * 4;
    const float* gB[BF];
#pragma unroll
    for (int i = 0; i < BF; i++)
        gB[i] = B + (size_t)(bn + ar + i * 64) * DD + aq * 4;

    const unsigned baseAh = smem_u32(&sA[0][0][0][0]);
    const unsigned baseAl = smem_u32(&sA[0][1][0][0]);
    const unsigned baseBh = smem_u32(&sB[0][0][0][0]);
    const unsigned baseBl = smem_u32(&sB[0][1][0][0]);
    const unsigned stageA = 2u * 64 * LWB;
    const unsigned stageB = 2u * BN * LWB;
    const int aRow = wm * 16 + (lane & 15);
    const int aColB = ((lane >> 4) & 1) * 16;
    const unsigned aOffH = baseAh + aRow * LWB + aColB;
    const unsigned aOffL = baseAl + aRow * LWB + aColB;
    const int bRow = wn * (BN / 2) + (lane & 7) + ((lane >> 4) & 1) * 8;
    const int bColB = ((lane >> 3) & 1) * 16;
    const unsigned bOffH = baseBh + bRow * LWB + bColB;
    const unsigned bOffL = baseBl + bRow * LWB + bColB;

    float acc[NFRAG][4];
#pragma unroll
    for (int t = 0; t < NFRAG; t++)
#pragma unroll
        for (int j = 0; j < 4; j++) acc[t][j] = 0.f;

    float4 a4, b4[BF];
    a4 = *(const float4*)gA;
#pragma unroll
    for (int i = 0; i < BF; i++) b4[i] = *(const float4*)gB[i];
    cvt_store(a4, &sA[0][0][ar][aq*4], &sA[0][1][ar][aq*4]);
#pragma unroll
    for (int i = 0; i < BF; i++)
        cvt_store(b4[i], &sB[0][0][ar + i*64][aq*4], &sB[0][1][ar + i*64][aq*4]);
    __syncthreads();

    const int NIT = DD / 16;
    for (int it = 0; it < NIT; it++) {
        const int cur = it & 1;
        const bool nx = (it + 1 < NIT);
        if (nx) {
            const int k0 = (it + 1) * 16;
            a4 = *(const float4*)(gA + k0);
#pragma unroll
            for (int i = 0; i < BF; i++) b4[i] = *(const float4*)(gB[i] + k0);
        }
        const unsigned soA = cur * stageA;
        const unsigned soB = cur * stageB;
        unsigned ah0,ah1,ah2,ah3, al0,al1,al2,al3;
        ldmat_x4(aOffH + soA, ah0, ah1, ah2, ah3);
        ldmat_x4(aOffL + soA, al0, al1, al2, al3);
#pragma unroll
        for (int p = 0; p < BN / 32; p++) {
            unsigned bh0,bh1,bh2,bh3, bl0,bl1,bl2,bl3;
            ldmat_x4(bOffH + soB + p * 16 * LWB, bh0, bh1, bh2, bh3);
            ldmat_x4(bOffL + soB + p * 16 * LWB, bl0, bl1, bl2, bl3);
            mma_bf16(acc[2*p],   ah0,ah1,ah2,ah3, bh0,bh1);
            mma_bf16(acc[2*p+1], ah0,ah1,ah2,ah3, bh2,bh3);
            mma_bf16(acc[2*p],   ah0,ah1,ah2,ah3, bl0,bl1);
            mma_bf16(acc[2*p+1], ah0,ah1,ah2,ah3, bl2,bl3);
            mma_bf16(acc[2*p],   al0,al1,al2,al3, bh0,bh1);
            mma_bf16(acc[2*p+1], al0,al1,al2,al3, bh2,bh3);
        }
        if (nx) {
            const int ns = cur ^ 1;
            cvt_store(a4, &sA[ns][0][ar][aq*4], &sA[ns][1][ar][aq*4]);
#pragma unroll
            for (int i = 0; i < BF; i++)
                cvt_store(b4[i], &sB[ns][0][ar + i*64][aq*4], &sB[ns][1][ar + i*64][aq*4]);
        }
        __syncthreads();
    }

#pragma unroll
    for (int t = 0; t < NFRAG; t++) {
        const int col = bn + wn * (BN / 2) + t * 8 + tig * 2;
        const int r0 = bm + wm * 16 + gid, r1 = r0 + 8;
        float2 v0 = make_float2(acc[t][0], acc[t][1]);
        float2 v1 = make_float2(acc[t][2], acc[t][3]);
        if (res) {
            float2 e0 = *(const float2*)&res[(size_t)r0 * DD + col];
            float2 e1 = *(const float2*)&res[(size_t)r1 * DD + col];
            v0.x += e0.x; v0.y += e0.y; v1.x += e1.x; v1.y += e1.y;
        }
        *(float2*)&C[(size_t)r0 * DD + col] = v0;
        *(float2*)&C[(size_t)r1 * DD + col] = v1;
        if (C2) {
            *(float2*)&C2[(size_t)r0 * DD + col] = v0;
            *(float2*)&C2[(size_t)r1 * DD + col] = v1;
        }
    }
}

__global__ void qkv_tc_kernel(const float* __restrict__ xn,
                              const float* __restrict__ qw, const float* __restrict__ kw,
                              const float* __restrict__ vw,
                              float* __restrict__ qb, float* __restrict__ kb,
                              float* __restrict__ vb)
{
    const float* B; float* C;
    if (blockIdx.z == 0)      { B = qw; C = qb; }
    else if (blockIdx.z == 1) { B = kw; C = kb; }
    else                      { B = vw; C = vb; }
    dense_core<64>(xn, B, C, nullptr, nullptr);
}

__global__ void oproj_tc_kernel(const float* __restrict__ ctx, const float* __restrict__ ow,
                                const float* __restrict__ x, float* __restrict__ x2,
                                float* __restrict__ out)
{
    dense_core<64>(ctx, ow, x2, x, out);
}

// ==================== v15 MoE core: BK=32, full-line loads, 80B rows ====================
// Warp layout as R4: 2m x 4n, warp tile 16x32 of the 32x128 accumulator block.
// Loads: 8 threads/row x float4 (full 128B lines). A: 32 rows; B: 128 rows (4 passes).

#define V15_FRAG_SETUP() \
    const unsigned sbase = smem_u32(dsm); \
    const int aRow = wm * 16 + (lane & 15); \
    const unsigned aOffH = sbase + V15_A_OFF(0,0) + aRow * RS + ((lane >> 4) & 1) * 16; \
    const unsigned aOffL = aOffH + 2560; \
    const int bRow = wn * 32 + (lane & 7) + ((lane >> 4) & 1) * 8; \
    const unsigned bOffH = sbase + V15_B_OFF(0,0) + bRow * RS + ((lane >> 3) & 1) * 16; \
    const unsigned bOffL = bOffH + 10240;

#define V15_COMPUTE(cur) do { \
    const unsigned soA = (cur) * 5120; \
    const unsigned soB = (cur) * 20480; \
    _Pragma("unroll") \
    for (int kk = 0; kk < 2; kk++) { \
        unsigned ah0,ah1,ah2,ah3, al0,al1,al2,al3; \
        ldmat_x4(aOffH + soA + kk * 32, ah0, ah1, ah2, ah3); \
        ldmat_x4(aOffL + soA + kk * 32, al0, al1, al2, al3); \
        _Pragma("unroll") \
        for (int p = 0; p < 2; p++) { \
            unsigned bh0,bh1,bh2,bh3, bl0,bl1,bl2,bl3; \
            ldmat_x4(bOffH + soB + p * 16 * RS + kk * 32, bh0, bh1, bh2, bh3); \
            ldmat_x4(bOffL + soB + p * 16 * RS + kk * 32, bl0, bl1, bl2, bl3); \
            mma_bf16(acc[2*p],   ah0,ah1,ah2,ah3, bh0,bh1); \
            mma_bf16(acc[2*p+1], ah0,ah1,ah2,ah3, bh2,bh3); \
            mma_bf16(acc[2*p],   ah0,ah1,ah2,ah3, bl0,bl1); \
            mma_bf16(acc[2*p+1], ah0,ah1,ah2,ah3, bl2,bl3); \
            mma_bf16(acc[2*p],   al0,al1,al2,al3, bh0,bh1); \
            mma_bf16(acc[2*p+1], al0,al1,al2,al3, bh2,bh3); \
        } \
    } \
} while (0)

#define V15_LOAD(k0) do { \
    a4 = *(const float4*)(gA + (k0)); \
    _Pragma("unroll") for (int f = 0; f < 4; f++) b4[f] = *(const float4*)(bP[f] + (k0)); \
} while (0)

// store: A row = tid>>3 (32 rows x 8 threads), byte col q*8; B rows (tid>>3)+f*32
#define V15_STORE(st) do { \
    cvt_store(a4, (__nv_bfloat16*)(dsm + V15_A_OFF(st,0) + lr8 * RS + q8 * 8), \
                  (__nv_bfloat16*)(dsm + V15_A_OFF(st,1) + lr8 * RS + q8 * 8)); \
    _Pragma("unroll") for (int f = 0; f < 4; f++) { \
        int rr = lr8 + f * 32; \
        cvt_store(b4[f], (__nv_bfloat16*)(dsm + V15_B_OFF(st,0) + rr * RS + q8 * 8), \
                         (__nv_bfloat16*)(dsm + V15_B_OFF(st,1) + rr * RS + q8 * 8)); } \
} while (0)

// ---- gate_up: 32 tokens x 64 cols (gate rows 0-63, up rows 64-127), K=2048 ----
__global__ __launch_bounds__(256, 2)
void moe_gate_up_v15(const float* __restrict__ x3, const float* __restrict__ w_gu,
                     const int* __restrict__ cnt, const int* __restrict__ tok,
                     const float* __restrict__ wgt, float* __restrict__ act)
{
    extern __shared__ __align__(16) char dsm[];
    const int e = blockIdx.z;
    const int nt = cnt[e];
    const int m0 = blockIdx.y * 32;
    if (m0 >= nt) return;
    const int n0 = blockIdx.x * 64;
    const int tid = threadIdx.x, lane = tid & 31, wid = tid >> 5;
    const int wm = wid & 1, wn = wid >> 1;
    const int gid = lane >> 2, tig = lane & 3;
    float* Cs = (float*)(dsm + 10240);  // 32 x 132 f32 = 16896 <= 40960 B region

    __shared__ int   stok[32];
    __shared__ float sw_[32];
    if (tid < 32) {
        int rr = min(m0 + tid, nt - 1);
        stok[tid] = tok[e * 256 + rr];
        sw_[tid]  = wgt[e * 256 + rr];
    }
    __syncthreads();

    const int lr8 = tid >> 3, q8 = tid & 7;
    const float* gA = x3 + (size_t)stok[lr8] * DD + q8 * 4;
    const float* Wg = w_gu + (size_t)e * (2 * DFF) * DD;
    const float* bP[4];
#pragma unroll
    for (int f = 0; f < 4; f++) {
        int r = lr8 + f * 32;
        bP[f] = ((r < 64) ? (Wg + (size_t)(n0 + r) * DD)
                          : (Wg + (size_t)(DFF + n0 + r - 64) * DD)) + q8 * 4;
    }

    V15_FRAG_SETUP();

    float acc[4][4];
#pragma unroll
    for (int t = 0; t < 4; t++)
#pragma unroll
        for (int j = 0; j < 4; j++) acc[t][j] = 0.f;

    float4 a4, b4[4];
    V15_LOAD(0);
    V15_STORE(0);
    __syncthreads();

    const int NIT = DD / 32;   // 64
    for (int it = 0; it < NIT; it++) {
        const int cur = it & 1;
        const bool nx = (it + 1 < NIT);
        if (nx) V15_LOAD((it + 1) * 32);
        V15_COMPUTE(cur);
        if (nx) V15_STORE(cur ^ 1);
        __syncthreads();
    }

    // stage accumulators: cols 0..63 gate, 64..127 up (R4 epilogue)
#pragma unroll
    for (int t = 0; t < 4; t++) {
        const int c = wn * 32 + t * 8 + tig * 2;
        const int r0 = wm * 16 + gid;
        Cs[r0 * 132 + c]       = acc[t][0];
        Cs[r0 * 132 + c + 1]   = acc[t][1];
        Cs[(r0+8) * 132 + c]   = acc[t][2];
        Cs[(r0+8) * 132 + c+1] = acc[t][3];
    }
    __syncthreads();

    const int m = tid >> 3;
    if (m0 + m < nt) {
        const float w = sw_[m];
        const int j0 = (tid & 7) * 8;
        const size_t base = ((size_t)(e * 256 + m0 + m)) * DFF + n0 + j0;
#pragma unroll
        for (int j = 0; j < 8; j++) {
            float g = Cs[m * 132 + j0 + j];
            float u = Cs[m * 132 + 64 + j0 + j];
            float sg = g / (1.f + expf(-g));
            act[base + j] = sg * u * w;
        }
    }
}

// ---- down: 32 tokens x 128 cols, K=1024, plain stores to part ----
__global__ __launch_bounds__(256, 2)
void moe_down_v15(const float* __restrict__ act, const float* __restrict__ w_down,
                  const int* __restrict__ cnt, float* __restrict__ part)
{
    extern __shared__ __align__(16) char dsm[];
    const int e = blockIdx.z;
    const int nt = cnt[e];
    const int m0 = blockIdx.y * 32;
    if (m0 >= nt) return;
    const int n0 = blockIdx.x * 128;
    const int tid = threadIdx.x, lane = tid & 31, wid = tid >> 5;
    const int wm = wid & 1, wn = wid >> 1;
    const int gid = lane >> 2, tig = lane & 3;

    const int lr8 = tid >> 3, q8 = tid & 7;
    // rows >= nt read in-bounds stale data; their partials are never gathered
    const float* gA = act + ((size_t)(e * 256 + m0 + lr8)) * DFF + q8 * 4;
    const float* W = w_down + (size_t)e * DD * DFF;
    const float* bP[4];
#pragma unroll
    for (int f = 0; f < 4; f++)
        bP[f] = W + (size_t)(n0 + lr8 + f * 32) * DFF + q8 * 4;

    V15_FRAG_SETUP();

    float acc[4][4];
#pragma unroll
    for (int t = 0; t < 4; t++)
#pragma unroll
        for (int j = 0; j < 4; j++) acc[t][j] = 0.f;

    float4 a4, b4[4];
    V15_LOAD(0);
    V15_STORE(0);
    __syncthreads();

    const int NIT = DFF / 32;   // 32
    for (int it = 0; it < NIT; it++) {
        const int cur = it & 1;
        const bool nx = (it + 1 < NIT);
        if (nx) V15_LOAD((it + 1) * 32);
        V15_COMPUTE(cur);
        if (nx) V15_STORE(cur ^ 1);
        __syncthreads();
    }

#pragma unroll
    for (int t = 0; t < 4; t++) {
        const int col = n0 + wn * 32 + t * 8 + tig * 2;
        const int r0 = wm * 16 + gid, r1 = r0 + 8;
        *(float2*)&part[(size_t)(e * 256 + m0 + r0) * DD + col] = make_float2(acc[t][0], acc[t][1]);
        *(float2*)&part[(size_t)(e * 256 + m0 + r1) * DD + col] = make_float2(acc[t][2], acc[t][3]);
    }
}

// ==================== host launch ====================
extern "C" void kernel_launch(void* const* d_in, const int* in_sizes, int n_in,
                              void* d_out, int out_size)
{
    const float* x    = (const float*)d_in[0];
    const float* ln1  = (const float*)d_in[1];
    const float* qw   = (const float*)d_in[2];
    const float* kw   = (const float*)d_in[3];
    const float* vw   = (const float*)d_in[4];
    const float* qn   = (const float*)d_in[5];
    const float* kn   = (const float*)d_in[6];
    const float* ow   = (const float*)d_in[7];
    const float* ln2  = (const float*)d_in[8];
    const float* gw   = (const float*)d_in[9];
    const float* guw  = (const float*)d_in[10];
    const float* dw   = (const float*)d_in[11];
    float* out = (float*)d_out;

    float *p_xn, *p_qb, *p_kb, *p_vb, *p_sc, *p_ctx, *p_x2, *p_x3, *p_act, *p_part, *p_wgt;
    int *p_cnt, *p_tok, *p_inv;
    cudaGetSymbolAddress((void**)&p_xn,  g_xn);
    cudaGetSymbolAddress((void**)&p_qb,  g_qb);
    cudaGetSymbolAddress((void**)&p_kb,  g_kb);
    cudaGetSymbolAddress((void**)&p_vb,  g_vb);
    cudaGetSymbolAddress((void**)&p_sc,  g_sc);
    cudaGetSymbolAddress((void**)&p_ctx, g_ctx);
    cudaGetSymbolAddress((void**)&p_x2,  g_x2);
    cudaGetSymbolAddress((void**)&p_x3,  g_x3);
    cudaGetSymbolAddress((void**)&p_act, g_act);
    cudaGetSymbolAddress((void**)&p_part, g_part);
    cudaGetSymbolAddress((void**)&p_cnt, g_cnt);
    cudaGetSymbolAddress((void**)&p_tok, g_tok);
    cudaGetSymbolAddress((void**)&p_wgt, g_wgt);
    cudaGetSymbolAddress((void**)&p_inv, g_inv);

    static int smem_set = 0;
    if (!smem_set) {
        cudaFuncSetAttribute(moe_gate_up_v15, cudaFuncAttributeMaxDynamicSharedMemorySize, V15_DSMEM);
        cudaFuncSetAttribute(moe_down_v15,    cudaFuncAttributeMaxDynamicSharedMemorySize, V15_DSMEM);
        smem_set = 1;
    }

    // #1: xn = rms(x, ln1)
    rms_kernel<<<TT, 256>>>(x, ln1, p_xn);

    // #2: q/k/v projections
    dim3 gqkv(DD / 64, TT / 64, 3);
    qkv_tc_kernel<<<gqkv, 256>>>(p_xn, qw, kw, vw, p_qb, p_kb, p_vb);

    // #3: fused q/k RMS + RoPE
    qk_norm_rope<<<TT, 256>>>(p_qb, p_kb, qn, kn);

    // #4: scores + causal
    dim3 gsc(TT / 64, TT / 64, NH);
    score_gemm<<<gsc, 256>>>(p_qb, p_kb, p_sc);

    // #5: softmax
    softmax_kernel<<<NH * TT, 256>>>(p_sc);

    // #6: ctx = P @ V
    dim3 gpv(HDIM / 64, TT / 64, NH);
    pv_gemm<<<gpv, 256>>>(p_sc, p_vb, p_ctx);

    // #7: x2 = x + ctx @ ow^T, dual-store into out
    dim3 go(DD / 64, TT / 64, 1);
    oproj_tc_kernel<<<go, 256>>>(p_ctx, ow, x, p_x2, out);

    // #8: x3 = rms(x2, ln2)
    rms_kernel<<<TT, 256>>>(p_x2, ln2, p_x3);

    // #9-10: router
    zero_cnt_kernel<<<1, 64>>>(p_cnt);
    router_kernel<<<TT, 256>>>(p_x3, gw, p_cnt, p_tok, p_wgt, p_inv);

    // #11: MoE gate_up (v15: BK=32, full-line loads)
    dim3 ggu(DFF / 64, 8, NE);
    moe_gate_up_v15<<<ggu, 256, V15_DSMEM>>>(p_x3, guw, p_cnt, p_tok, p_wgt, p_act);

    // #12: MoE down (v15)
    dim3 gdn(DD / 128, 8, NE);
    moe_down_v15<<<gdn, 256, V15_DSMEM>>>(p_act, dw, p_cnt, p_part);

    // #13: gather partials into out
    gather_kernel<<<TT, 256>>>(p_part, p_inv, out);
}

// round 16
// speedup vs baseline: 1.0988x; 1.0345x over previous
#include <cuda_runtime.h>
#include <cuda_bf16.h>
#include <math.h>

#define TT 256
#define DD 2048
#define NH 16
#define HDIM 128
#define NE 64
#define TOPK 8
#define DFF 1024
#define EPSF 1e-5f
#define ASCALE 0.08838834764831845f
#define NEGINF -3.4028234663852886e38f

#define RS 80   // smem row stride bytes (64B data + 16B pad), conflict-free for ldsm

// v15 MoE smem: BK=32. A: [st2][pl2][32][80] plane 2560, tot 10240.
// B: [st2][pl2][128][80] plane 10240, tot 40960. total 51200.
#define V15_A_OFF(st, pl)  (((st) * 2 + (pl)) * 2560)
#define V15_B_OFF(st, pl)  (10240 + ((st) * 2 + (pl)) * 10240)
#define V15_DSMEM 51200

// dense32 smem: BK=32. A: [st2][pl2][64][80] plane 5120; B same. total 40960.
#define D16_APL 5120
#define D16_B0  20480
#define D16_DSMEM 40960

// ---------------- scratch ----------------
__device__ float g_xn[TT*DD];
__device__ float g_qb[TT*DD];
__device__ float g_kb[TT*DD];
__device__ float g_vb[TT*DD];
__device__ float g_sc[NH*TT*TT];
__device__ float g_ctx[TT*DD];
__device__ float g_x2[TT*DD];
__device__ float g_x3[TT*DD];
__device__ float g_act[(size_t)NE*256*DFF];
__device__ float g_part[(size_t)NE*256*DD];
__device__ int   g_cnt[NE];
__device__ int   g_tok[NE*256];
__device__ float g_wgt[NE*256];
__device__ int   g_inv[TT*TOPK];

// ==================== PTX helpers ====================
__device__ __forceinline__ unsigned smem_u32(const void* p) {
    return (unsigned)__cvta_generic_to_shared(p);
}
__device__ __forceinline__ void ldmat_x4(unsigned addr, unsigned &r0, unsigned &r1,
                                         unsigned &r2, unsigned &r3) {
    asm volatile("ldmatrix.sync.aligned.m8n8.x4.shared.b16 {%0,%1,%2,%3}, [%4];"
        : "=r"(r0), "=r"(r1), "=r"(r2), "=r"(r3) : "r"(addr));
}
__device__ __forceinline__ void mma_bf16(float* c,
    unsigned a0, unsigned a1, unsigned a2, unsigned a3, unsigned b0, unsigned b1) {
    asm volatile("mma.sync.aligned.m16n8k16.row.col.f32.bf16.bf16.f32 "
        "{%0,%1,%2,%3}, {%4,%5,%6,%7}, {%8,%9}, {%0,%1,%2,%3};"
        : "+f"(c[0]), "+f"(c[1]), "+f"(c[2]), "+f"(c[3])
        : "r"(a0), "r"(a1), "r"(a2), "r"(a3), "r"(b0), "r"(b1));
}
__device__ __forceinline__ void split_pair(float x0, float x1, unsigned &h, unsigned &l) {
    asm("cvt.rn.bf16x2.f32 %0, %1, %2;" : "=r"(h) : "f"(x1), "f"(x0));
    float h0 = __uint_as_float(h << 16);
    float h1 = __uint_as_float(h & 0xffff0000u);
    float r0 = x0 - h0, r1 = x1 - h1;
    asm("cvt.rn.bf16x2.f32 %0, %1, %2;" : "=r"(l) : "f"(r1), "f"(r0));
}
__device__ __forceinline__ void cvt_store(float4 v, __nv_bfloat16* ph, __nv_bfloat16* pl) {
    unsigned h0, l0, h1, l1;
    split_pair(v.x, v.y, h0, l0);
    split_pair(v.z, v.w, h1, l1);
    *(uint2*)ph = make_uint2(h0, h1);
    *(uint2*)pl = make_uint2(l0, l1);
}

// ==================== elementwise ====================
__global__ void rms_kernel(const float* __restrict__ in, const float* __restrict__ w,
                           float* __restrict__ out)
{
    int row = blockIdx.x;
    const float* xr = in + (size_t)row * DD;
    float ss = 0.f;
    for (int i = threadIdx.x; i < DD; i += 256) { float v = xr[i]; ss += v * v; }
    __shared__ float red[256];
    red[threadIdx.x] = ss; __syncthreads();
    for (int s = 128; s > 0; s >>= 1) {
        if (threadIdx.x < s) red[threadIdx.x] += red[threadIdx.x + s];
        __syncthreads();
    }
    float r = rsqrtf(red[0] / (float)DD + EPSF);
    for (int i = threadIdx.x; i < DD; i += 256)
        out[(size_t)row * DD + i] = xr[i] * r * w[i];
}

__global__ void qk_norm_rope(float* __restrict__ q, float* __restrict__ k,
                             const float* __restrict__ qn_w, const float* __restrict__ kn_w)
{
    int t = blockIdx.x;
    float* qr = q + (size_t)t * DD;
    float* kr = k + (size_t)t * DD;
    int tid = threadIdx.x;
    float sq = 0.f, sk = 0.f;
    for (int i = tid; i < DD; i += 256) {
        float a = qr[i]; sq += a * a;
        float b = kr[i]; sk += b * b;
    }
    __shared__ float rq_s[256], rk_s[256];
    rq_s[tid] = sq; rk_s[tid] = sk; __syncthreads();
    for (int s = 128; s > 0; s >>= 1) {
        if (tid < s) { rq_s[tid] += rq_s[tid + s]; rk_s[tid] += rk_s[tid + s]; }
        __syncthreads();
    }
    float rq = rsqrtf(rq_s[0] / (float)DD + EPSF);
    float rk = rsqrtf(rk_s[0] / (float)DD + EPSF);
    for (int p = tid; p < NH * 64; p += 256) {
        int h = p >> 6, i = p & 63;
        float inv = __expf(-((float)i / 64.0f) * 9.210340371976184f);
        float ang = (float)t * inv;
        float c = cosf(ang), s = sinf(ang);
        int base = h * HDIM;
        float q1 = qr[base + i]      * rq * qn_w[base + i];
        float q2 = qr[base + 64 + i] * rq * qn_w[base + 64 + i];
        qr[base + i]      = q1 * c - q2 * s;
        qr[base + 64 + i] = q1 * s + q2 * c;
        float k1 = kr[base + i]      * rk * kn_w[base + i];
        float k2 = kr[base + 64 + i] * rk * kn_w[base + 64 + i];
        kr[base + i]      = k1 * c - k2 * s;
        kr[base + 64 + i] = k1 * s + k2 * c;
    }
}

__global__ void softmax_kernel(float* __restrict__ s)
{
    int row = blockIdx.x;
    float* p = s + (size_t)row * TT;
    int i = threadIdx.x;
    float v = p[i];
    __shared__ float red[256];
    red[i] = v; __syncthreads();
    for (int st = 128; st > 0; st >>= 1) {
        if (i < st) red[i] = fmaxf(red[i], red[i + st]);
        __syncthreads();
    }
    float m = red[0]; __syncthreads();
    float e = expf(v - m);
    red[i] = e; __syncthreads();
    for (int st = 128; st > 0; st >>= 1) {
        if (i < st) red[i] += red[i + st];
        __syncthreads();
    }
    p[i] = e / red[0];
}

__global__ void zero_cnt_kernel(int* cnt)
{
    if (threadIdx.x < NE) cnt[threadIdx.x] = 0;
}

__global__ void router_kernel(const float* __restrict__ x3, const float* __restrict__ gw,
                              int* __restrict__ cnt, int* __restrict__ tok,
                              float* __restrict__ wgt, int* __restrict__ inv)
{
    int t = blockIdx.x;
    __shared__ float xr[DD];
    __shared__ float lg[NE];
    for (int i = threadIdx.x; i < DD; i += blockDim.x) xr[i] = x3[(size_t)t * DD + i];
    __syncthreads();
    {
        int e = threadIdx.x >> 2, p4 = threadIdx.x & 3;
        const float* wrow = gw + (size_t)e * DD + p4 * 512;
        const float* xp = xr + p4 * 512;
        float acc = 0.f;
        for (int j = 0; j < 512; j++) acc += xp[j] * wrow[j];
        acc += __shfl_down_sync(0xffffffffu, acc, 1, 4);
        acc += __shfl_down_sync(0xffffffffu, acc, 2, 4);
        if (p4 == 0) lg[e] = acc;
    }
    __syncthreads();
    if (threadIdx.x == 0) {
        float mx = -1e30f;
        for (int e = 0; e < NE; e++) mx = fmaxf(mx, lg[e]);
        float sum = 0.f;
        for (int e = 0; e < NE; e++) { lg[e] = expf(lg[e] - mx); sum += lg[e]; }
        bool used[NE];
        for (int e = 0; e < NE; e++) used[e] = false;
        for (int s = 0; s < TOPK; s++) {
            int bi = 0; float bv = -1.f;
            for (int e = 0; e < NE; e++)
                if (!used[e] && lg[e] > bv) { bv = lg[e]; bi = e; }
            used[bi] = true;
            int pos = atomicAdd(&cnt[bi], 1);
            tok[bi * 256 + pos] = t;
            wgt[bi * 256 + pos] = bv / sum;
            inv[t * TOPK + s] = bi * 256 + pos;
        }
    }
}

__global__ void gather_kernel(const float* __restrict__ part, const int* __restrict__ inv,
                              float* __restrict__ out)
{
    int t = blockIdx.x;
    __shared__ int iv[TOPK];
    if (threadIdx.x < TOPK) iv[threadIdx.x] = inv[t * TOPK + threadIdx.x];
    __syncthreads();
    int d = threadIdx.x * 8;
    float4 v0 = *(const float4*)&out[(size_t)t * DD + d];
    float4 v1 = *(const float4*)&out[(size_t)t * DD + d + 4];
#pragma unroll
    for (int s = 0; s < TOPK; s++) {
        const float* p = part + (size_t)iv[s] * DD + d;
        float4 p0 = *(const float4*)p;
        float4 p1 = *(const float4*)(p + 4);
        v0.x += p0.x; v0.y += p0.y; v0.z += p0.z; v0.w += p0.w;
        v1.x += p1.x; v1.y += p1.y; v1.z += p1.z; v1.w += p1.w;
    }
    *(float4*)&out[(size_t)t * DD + d]     = v0;
    *(float4*)&out[(size_t)t * DD + d + 4] = v1;
}

// ==================== attention SIMT GEMMs (proven) ====================
__global__ void score_gemm(const float* __restrict__ Q, const float* __restrict__ Kk,
                           float* __restrict__ S)
{
    int h = blockIdx.z;
    const float* A = Q + h * HDIM;
    const float* B = Kk + h * HDIM;
    float* C = S + (size_t)h * TT * TT;
    __shared__ float As[16][64];
    __shared__ float Bs[16][64];
    int bm = blockIdx.y * 64, bn = blockIdx.x * 64;
    int tid = threadIdx.x;
    int lr = tid >> 2, lc = tid & 3;
    int ty = tid >> 4, tx = tid & 15;
    float acc[4][4];
#pragma unroll
    for (int i = 0; i < 4; i++)
#pragma unroll
        for (int j = 0; j < 4; j++) acc[i][j] = 0.f;
    for (int k0 = 0; k0 < HDIM; k0 += 16) {
        float4 a4 = *(const float4*)(A + (size_t)(bm + lr) * DD + k0 + lc * 4);
        float4 b4 = *(const float4*)(B + (size_t)(bn + lr) * DD + k0 + lc * 4);
        As[lc*4+0][lr] = a4.x; As[lc*4+1][lr] = a4.y; As[lc*4+2][lr] = a4.z; As[lc*4+3][lr] = a4.w;
        Bs[lc*4+0][lr] = b4.x; Bs[lc*4+1][lr] = b4.y; Bs[lc*4+2][lr] = b4.z; Bs[lc*4+3][lr] = b4.w;
        __syncthreads();
#pragma unroll
        for (int kk = 0; kk < 16; kk++) {
            float4 av = *(const float4*)&As[kk][ty*4];
            float4 bv = *(const float4*)&Bs[kk][tx*4];
            float ar[4] = {av.x, av.y, av.z, av.w};
            float br[4] = {bv.x, bv.y, bv.z, bv.w};
#pragma unroll
            for (int i = 0; i < 4; i++)
#pragma unroll
                for (int j = 0; j < 4; j++) acc[i][j] += ar[i] * br[j];
        }
        __syncthreads();
    }
#pragma unroll
    for (int i = 0; i < 4; i++) {
        int row = bm + ty*4 + i;
#pragma unroll
        for (int j = 0; j < 4; j++) {
            int col = bn + tx*4 + j;
            float v = acc[i][j] * ASCALE;
            if (col > row) v = NEGINF;
            C[(size_t)row * TT + col] = v;
        }
    }
}

__global__ void pv_gemm(const float* __restrict__ P, const float* __restrict__ V,
                        float* __restrict__ CTX)
{
    int h = blockIdx.z;
    const float* A = P + (size_t)h * TT * TT;
    const float* B = V + h * HDIM;
    float* C = CTX + h * HDIM;
    __shared__ float As[16][64];
    __shared__ float Bs[16][64];
    int bm = blockIdx.y * 64, bn = blockIdx.x * 64;
    int tid = threadIdx.x;
    int lr = tid >> 2, lc = tid & 3;
    int ty = tid >> 4, tx = tid & 15;
    float acc[4][4];
#pragma unroll
    for (int i = 0; i < 4; i++)
#pragma unroll
        for (int j = 0; j < 4; j++) acc[i][j] = 0.f;
    for (int k0 = 0; k0 < TT; k0 += 16) {
        float4 a4 = *(const float4*)(A + (size_t)(bm + lr) * TT + k0 + lc * 4);
        As[lc*4+0][lr] = a4.x; As[lc*4+1][lr] = a4.y; As[lc*4+2][lr] = a4.z; As[lc*4+3][lr] = a4.w;
#pragma unroll
        for (int i = 0; i < 4; i++) {
            int kr = i * 4 + (tid >> 6);
            Bs[kr][tid & 63] = B[(size_t)(k0 + kr) * DD + bn + (tid & 63)];
        }
        __syncthreads();
#pragma unroll
        for (int kk = 0; kk < 16; kk++) {
            float4 av = *(const float4*)&As[kk][ty*4];
            float4 bv = *(const float4*)&Bs[kk][tx*4];
            float ar[4] = {av.x, av.y, av.z, av.w};
            float br[4] = {bv.x, bv.y, bv.z, bv.w};
#pragma unroll
            for (int i = 0; i < 4; i++)
#pragma unroll
                for (int j = 0; j < 4; j++) acc[i][j] += ar[i] * br[j];
        }
        __syncthreads();
    }
#pragma unroll
    for (int i = 0; i < 4; i++) {
        int row = bm + ty*4 + i;
#pragma unroll
        for (int j = 0; j < 4; j++)
            C[(size_t)row * DD + bn + tx*4 + j] = acc[i][j];
    }
}

// ==================== dense32: bf16x3 NT GEMM, BK=32, BM=BN=64 ====================
__device__ __forceinline__ void dense32_core(
    const float* __restrict__ A, const float* __restrict__ B,
    float* __restrict__ C, const float* __restrict__ res, float* __restrict__ C2)
{
    extern __shared__ __align__(16) char dsm[];
    const int tid = threadIdx.x;
    const int lane = tid & 31, wid = tid >> 5;
    const int wm = wid & 3, wn = wid >> 2;
    const int gid = lane >> 2, tig = lane & 3;
    const int bm = blockIdx.y * 64, bn = blockIdx.x * 64;

    const int lr8 = tid >> 3, q8 = tid & 7;
    const float* gA0 = A + (size_t)(bm + lr8) * DD + q8 * 4;
    const float* gA1 = A + (size_t)(bm + lr8 + 32) * DD + q8 * 4;
    const float* gB0 = B + (size_t)(bn + lr8) * DD + q8 * 4;
    const float* gB1 = B + (size_t)(bn + lr8 + 32) * DD + q8 * 4;

    const unsigned sbase = smem_u32(dsm);
    const int aRow = wm * 16 + (lane & 15);
    const unsigned aOffH = sbase + aRow * RS + ((lane >> 4) & 1) * 16;
    const unsigned aOffL = aOffH + D16_APL;
    const int bRow = wn * 32 + (lane & 7) + ((lane >> 4) & 1) * 8;
    const unsigned bOffH = sbase + D16_B0 + bRow * RS + ((lane >> 3) & 1) * 16;
    const unsigned bOffL = bOffH + D16_APL;

    float acc[4][4];
#pragma unroll
    for (int t = 0; t < 4; t++)
#pragma unroll
        for (int j = 0; j < 4; j++) acc[t][j] = 0.f;

    float4 a40, a41, b40, b41;
#define D16_LOAD(k0) do { \
    a40 = *(const float4*)(gA0 + (k0)); a41 = *(const float4*)(gA1 + (k0)); \
    b40 = *(const float4*)(gB0 + (k0)); b41 = *(const float4*)(gB1 + (k0)); \
} while (0)
#define D16_STORE(st) do { \
    cvt_store(a40, (__nv_bfloat16*)(dsm + (st)*10240 + lr8 * RS + q8 * 8), \
                   (__nv_bfloat16*)(dsm + (st)*10240 + D16_APL + lr8 * RS + q8 * 8)); \
    cvt_store(a41, (__nv_bfloat16*)(dsm + (st)*10240 + (lr8+32) * RS + q8 * 8), \
                   (__nv_bfloat16*)(dsm + (st)*10240 + D16_APL + (lr8+32) * RS + q8 * 8)); \
    cvt_store(b40, (__nv_bfloat16*)(dsm + D16_B0 + (st)*10240 + lr8 * RS + q8 * 8), \
                   (__nv_bfloat16*)(dsm + D16_B0 + (st)*10240 + D16_APL + lr8 * RS + q8 * 8)); \
    cvt_store(b41, (__nv_bfloat16*)(dsm + D16_B0 + (st)*10240 + (lr8+32) * RS + q8 * 8), \
                   (__nv_bfloat16*)(dsm + D16_B0 + (st)*10240 + D16_APL + (lr8+32) * RS + q8 * 8)); \
} while (0)

    D16_LOAD(0);
    D16_STORE(0);
    __syncthreads();

    const int NIT = DD / 32;   // 64
    for (int it = 0; it < NIT; it++) {
        const int cur = it & 1;
        const bool nx = (it + 1 < NIT);
        if (nx) D16_LOAD((it + 1) * 32);
        {
            const unsigned soA = cur * 10240;
            const unsigned soB = cur * 10240;
#pragma unroll
            for (int kk = 0; kk < 2; kk++) {
                unsigned ah0,ah1,ah2,ah3, al0,al1,al2,al3;
                ldmat_x4(aOffH + soA + kk * 32, ah0, ah1, ah2, ah3);
                ldmat_x4(aOffL + soA + kk * 32, al0, al1, al2, al3);
#pragma unroll
                for (int p = 0; p < 2; p++) {
                    unsigned bh0,bh1,bh2,bh3, bl0,bl1,bl2,bl3;
                    ldmat_x4(bOffH + soB + p * 16 * RS + kk * 32, bh0, bh1, bh2, bh3);
                    ldmat_x4(bOffL + soB + p * 16 * RS + kk * 32, bl0, bl1, bl2, bl3);
                    mma_bf16(acc[2*p],   ah0,ah1,ah2,ah3, bh0,bh1);
                    mma_bf16(acc[2*p+1], ah0,ah1,ah2,ah3, bh2,bh3);
                    mma_bf16(acc[2*p],   ah0,ah1,ah2,ah3, bl0,bl1);
                    mma_bf16(acc[2*p+1], ah0,ah1,ah2,ah3, bl2,bl3);
                    mma_bf16(acc[2*p],   al0,al1,al2,al3, bh0,bh1);
                    mma_bf16(acc[2*p+1], al0,al1,al2,al3, bh2,bh3);
                }
            }
        }
        if (nx) D16_STORE(cur ^ 1);
        __syncthreads();
    }

#pragma unroll
    for (int t = 0; t < 4; t++) {
        const int col = bn + wn * 32 + t * 8 + tig * 2;
        const int r0 = bm + wm * 16 + gid, r1 = r0 + 8;
        float2 v0 = make_float2(acc[t][0], acc[t][1]);
        float2 v1 = make_float2(acc[t][2], acc[t][3]);
        if (res) {
            float2 e0 = *(const float2*)&res[(size_t)r0 * DD + col];
            float2 e1 = *(const float2*)&res[(size_t)r1 * DD + col];
            v0.x += e0.x; v0.y += e0.y; v1.x += e1.x; v1.y += e1.y;
        }
        *(float2*)&C[(size_t)r0 * DD + col] = v0;
        *(float2*)&C[(size_t)r1 * DD + col] = v1;
        if (C2) {
            *(float2*)&C2[(size_t)r0 * DD + col] = v0;
            *(float2*)&C2[(size_t)r1 * DD + col] = v1;
        }
    }
#undef D16_LOAD
#undef D16_STORE
}

__global__ __launch_bounds__(256, 2)
void qkv_tc_kernel(const float* __restrict__ xn,
                   const float* __restrict__ qw, const float* __restrict__ kw,
                   const float* __restrict__ vw,
                   float* __restrict__ qb, float* __restrict__ kb,
                   float* __restrict__ vb)
{
    const float* B; float* C;
    if (blockIdx.z == 0)      { B = qw; C = qb; }
    else if (blockIdx.z == 1) { B = kw; C = kb; }
    else                      { B = vw; C = vb; }
    dense32_core(xn, B, C, nullptr, nullptr);
}

__global__ __launch_bounds__(256, 2)
void oproj_tc_kernel(const float* __restrict__ ctx, const float* __restrict__ ow,
                     const float* __restrict__ x, float* __restrict__ x2,
                     float* __restrict__ out)
{
    dense32_core(ctx, ow, x2, x, out);
}

// ==================== v15 MoE (proven 922 build) ====================
#define V15_FRAG_SETUP() \
    const unsigned sbase = smem_u32(dsm); \
    const int aRow = wm * 16 + (lane & 15); \
    const unsigned aOffH = sbase + V15_A_OFF(0,0) + aRow * RS + ((lane >> 4) & 1) * 16; \
    const unsigned aOffL = aOffH + 2560; \
    const int bRow = wn * 32 + (lane & 7) + ((lane >> 4) & 1) * 8; \
    const unsigned bOffH = sbase + V15_B_OFF(0,0) + bRow * RS + ((lane >> 3) & 1) * 16; \
    const unsigned bOffL = bOffH + 10240;

#define V15_COMPUTE(cur) do { \
    const unsigned soA = (cur) * 5120; \
    const unsigned soB = (cur) * 20480; \
    _Pragma("unroll") \
    for (int kk = 0; kk < 2; kk++) { \
        unsigned ah0,ah1,ah2,ah3, al0,al1,al2,al3; \
        ldmat_x4(aOffH + soA + kk * 32, ah0, ah1, ah2, ah3); \
        ldmat_x4(aOffL + soA + kk * 32, al0, al1, al2, al3); \
        _Pragma("unroll") \
        for (int p = 0; p < 2; p++) { \
            unsigned bh0,bh1,bh2,bh3, bl0,bl1,bl2,bl3; \
            ldmat_x4(bOffH + soB + p * 16 * RS + kk * 32, bh0, bh1, bh2, bh3); \
            ldmat_x4(bOffL + soB + p * 16 * RS + kk * 32, bl0, bl1, bl2, bl3); \
            mma_bf16(acc[2*p],   ah0,ah1,ah2,ah3, bh0,bh1); \
            mma_bf16(acc[2*p+1], ah0,ah1,ah2,ah3, bh2,bh3); \
            mma_bf16(acc[2*p],   ah0,ah1,ah2,ah3, bl0,bl1); \
            mma_bf16(acc[2*p+1], ah0,ah1,ah2,ah3, bl2,bl3); \
            mma_bf16(acc[2*p],   al0,al1,al2,al3, bh0,bh1); \
            mma_bf16(acc[2*p+1], al0,al1,al2,al3, bh2,bh3); \
        } \
    } \
} while (0)

#define V15_LOAD(k0) do { \
    a4 = *(const float4*)(gA + (k0)); \
    _Pragma("unroll") for (int f = 0; f < 4; f++) b4[f] = *(const float4*)(bP[f] + (k0)); \
} while (0)

#define V15_STORE(st) do { \
    cvt_store(a4, (__nv_bfloat16*)(dsm + V15_A_OFF(st,0) + lr8 * RS + q8 * 8), \
                  (__nv_bfloat16*)(dsm + V15_A_OFF(st,1) + lr8 * RS + q8 * 8)); \
    _Pragma("unroll") for (int f = 0; f < 4; f++) { \
        int rr = lr8 + f * 32; \
        cvt_store(b4[f], (__nv_bfloat16*)(dsm + V15_B_OFF(st,0) + rr * RS + q8 * 8), \
                         (__nv_bfloat16*)(dsm + V15_B_OFF(st,1) + rr * RS + q8 * 8)); } \
} while (0)

__global__ __launch_bounds__(256, 2)
void moe_gate_up_v15(const float* __restrict__ x3, const float* __restrict__ w_gu,
                     const int* __restrict__ cnt, const int* __restrict__ tok,
                     const float* __restrict__ wgt, float* __restrict__ act)
{
    extern __shared__ __align__(16) char dsm[];
    const int e = blockIdx.z;
    const int nt = cnt[e];
    const int m0 = blockIdx.y * 32;
    if (m0 >= nt) return;
    const int n0 = blockIdx.x * 64;
    const int tid = threadIdx.x, lane = tid & 31, wid = tid >> 5;
    const int wm = wid & 1, wn = wid >> 1;
    const int gid = lane >> 2, tig = lane & 3;
    float* Cs = (float*)(dsm + 10240);

    __shared__ int   stok[32];
    __shared__ float sw_[32];
    if (tid < 32) {
        int rr = min(m0 + tid, nt - 1);
        stok[tid] = tok[e * 256 + rr];
        sw_[tid]  = wgt[e * 256 + rr];
    }
    __syncthreads();

    const int lr8 = tid >> 3, q8 = tid & 7;
    const float* gA = x3 + (size_t)stok[lr8] * DD + q8 * 4;
    const float* Wg = w_gu + (size_t)e * (2 * DFF) * DD;
    const float* bP[4];
#pragma unroll
    for (int f = 0; f < 4; f++) {
        int r = lr8 + f * 32;
        bP[f] = ((r < 64) ? (Wg + (size_t)(n0 + r) * DD)
                          : (Wg + (size_t)(DFF + n0 + r - 64) * DD)) + q8 * 4;
    }

    V15_FRAG_SETUP();

    float acc[4][4];
#pragma unroll
    for (int t = 0; t < 4; t++)
#pragma unroll
        for (int j = 0; j < 4; j++) acc[t][j] = 0.f;

    float4 a4, b4[4];
    V15_LOAD(0);
    V15_STORE(0);
    __syncthreads();

    const int NIT = DD / 32;
    for (int it = 0; it < NIT; it++) {
        const int cur = it & 1;
        const bool nx = (it + 1 < NIT);
        if (nx) V15_LOAD((it + 1) * 32);
        V15_COMPUTE(cur);
        if (nx) V15_STORE(cur ^ 1);
        __syncthreads();
    }

#pragma unroll
    for (int t = 0; t < 4; t++) {
        const int c = wn * 32 + t * 8 + tig * 2;
        const int r0 = wm * 16 + gid;
        Cs[r0 * 132 + c]       = acc[t][0];
        Cs[r0 * 132 + c + 1]   = acc[t][1];
        Cs[(r0+8) * 132 + c]   = acc[t][2];
        Cs[(r0+8) * 132 + c+1] = acc[t][3];
    }
    __syncthreads();

    const int m = tid >> 3;
    if (m0 + m < nt) {
        const float w = sw_[m];
        const int j0 = (tid & 7) * 8;
        const size_t base = ((size_t)(e * 256 + m0 + m)) * DFF + n0 + j0;
#pragma unroll
        for (int j = 0; j < 8; j++) {
            float g = Cs[m * 132 + j0 + j];
            float u = Cs[m * 132 + 64 + j0 + j];
            float sg = g / (1.f + expf(-g));
            act[base + j] = sg * u * w;
        }
    }
}

__global__ __launch_bounds__(256, 2)
void moe_down_v15(const float* __restrict__ act, const float* __restrict__ w_down,
                  const int* __restrict__ cnt, float* __restrict__ part)
{
    extern __shared__ __align__(16) char dsm[];
    const int e = blockIdx.z;
    const int nt = cnt[e];
    const int m0 = blockIdx.y * 32;
    if (m0 >= nt) return;
    const int n0 = blockIdx.x * 128;
    const int tid = threadIdx.x, lane = tid & 31, wid = tid >> 5;
    const int wm = wid & 1, wn = wid >> 1;
    const int gid = lane >> 2, tig = lane & 3;

    const int lr8 = tid >> 3, q8 = tid & 7;
    const float* gA = act + ((size_t)(e * 256 + m0 + lr8)) * DFF + q8 * 4;
    const float* W = w_down + (size_t)e * DD * DFF;
    const float* bP[4];
#pragma unroll
    for (int f = 0; f < 4; f++)
        bP[f] = W + (size_t)(n0 + lr8 + f * 32) * DFF + q8 * 4;

    V15_FRAG_SETUP();

    float acc[4][4];
#pragma unroll
    for (int t = 0; t < 4; t++)
#pragma unroll
        for (int j = 0; j < 4; j++) acc[t][j] = 0.f;

    float4 a4, b4[4];
    V15_LOAD(0);
    V15_STORE(0);
    __syncthreads();

    const int NIT = DFF / 32;
    for (int it = 0; it < NIT; it++) {
        const int cur = it & 1;
        const bool nx = (it + 1 < NIT);
        if (nx) V15_LOAD((it + 1) * 32);
        V15_COMPUTE(cur);
        if (nx) V15_STORE(cur ^ 1);
        __syncthreads();
    }

#pragma unroll
    for (int t = 0; t < 4; t++) {
        const int col = n0 + wn * 32 + t * 8 + tig * 2;
        const int r0 = wm * 16 + gid, r1 = r0 + 8;
        *(float2*)&part[(size_t)(e * 256 + m0 + r0) * DD + col] = make_float2(acc[t][0], acc[t][1]);
        *(float2*)&part[(size_t)(e * 256 + m0 + r1) * DD + col] = make_float2(acc[t][2], acc[t][3]);
    }
}

// ==================== host launch ====================
extern "C" void kernel_launch(void* const* d_in, const int* in_sizes, int n_in,
                              void* d_out, int out_size)
{
    const float* x    = (const float*)d_in[0];
    const float* ln1  = (const float*)d_in[1];
    const float* qw   = (const float*)d_in[2];
    const float* kw   = (const float*)d_in[3];
    const float* vw   = (const float*)d_in[4];
    const float* qn   = (const float*)d_in[5];
    const float* kn   = (const float*)d_in[6];
    const float* ow   = (const float*)d_in[7];
    const float* ln2  = (const float*)d_in[8];
    const float* gw   = (const float*)d_in[9];
    const float* guw  = (const float*)d_in[10];
    const float* dw   = (const float*)d_in[11];
    float* out = (float*)d_out;

    float *p_xn, *p_qb, *p_kb, *p_vb, *p_sc, *p_ctx, *p_x2, *p_x3, *p_act, *p_part, *p_wgt;
    int *p_cnt, *p_tok, *p_inv;
    cudaGetSymbolAddress((void**)&p_xn,  g_xn);
    cudaGetSymbolAddress((void**)&p_qb,  g_qb);
    cudaGetSymbolAddress((void**)&p_kb,  g_kb);
    cudaGetSymbolAddress((void**)&p_vb,  g_vb);
    cudaGetSymbolAddress((void**)&p_sc,  g_sc);
    cudaGetSymbolAddress((void**)&p_ctx, g_ctx);
    cudaGetSymbolAddress((void**)&p_x2,  g_x2);
    cudaGetSymbolAddress((void**)&p_x3,  g_x3);
    cudaGetSymbolAddress((void**)&p_act, g_act);
    cudaGetSymbolAddress((void**)&p_part, g_part);
    cudaGetSymbolAddress((void**)&p_cnt, g_cnt);
    cudaGetSymbolAddress((void**)&p_tok, g_tok);
    cudaGetSymbolAddress((void**)&p_wgt, g_wgt);
    cudaGetSymbolAddress((void**)&p_inv, g_inv);

    static int smem_set = 0;
    if (!smem_set) {
        cudaFuncSetAttribute(moe_gate_up_v15, cudaFuncAttributeMaxDynamicSharedMemorySize, V15_DSMEM);
        cudaFuncSetAttribute(moe_down_v15,    cudaFuncAttributeMaxDynamicSharedMemorySize, V15_DSMEM);
        cudaFuncSetAttribute(qkv_tc_kernel,   cudaFuncAttributeMaxDynamicSharedMemorySize, D16_DSMEM);
        cudaFuncSetAttribute(oproj_tc_kernel, cudaFuncAttributeMaxDynamicSharedMemorySize, D16_DSMEM);
        smem_set = 1;
    }

    // #1: xn = rms(x, ln1)
    rms_kernel<<<TT, 256>>>(x, ln1, p_xn);

    // #2: q/k/v projections (BK=32 dense core, 384 CTAs)
    dim3 gqkv(DD / 64, TT / 64, 3);
    qkv_tc_kernel<<<gqkv, 256, D16_DSMEM>>>(p_xn, qw, kw, vw, p_qb, p_kb, p_vb);

    // #3: fused q/k RMS + RoPE
    qk_norm_rope<<<TT, 256>>>(p_qb, p_kb, qn, kn);

    // #4: scores + causal
    dim3 gsc(TT / 64, TT / 64, NH);
    score_gemm<<<gsc, 256>>>(p_qb, p_kb, p_sc);

    // #5: softmax
    softmax_kernel<<<NH * TT, 256>>>(p_sc);

    // #6: ctx = P @ V
    dim3 gpv(HDIM / 64, TT / 64, NH);
    pv_gemm<<<gpv, 256>>>(p_sc, p_vb, p_ctx);

    // #7: x2 = x + ctx @ ow^T, dual-store into out
    dim3 go(DD / 64, TT / 64, 1);
    oproj_tc_kernel<<<go, 256, D16_DSMEM>>>(p_ctx, ow, x, p_x2, out);

    // #8: x3 = rms(x2, ln2)
    rms_kernel<<<TT, 256>>>(p_x2, ln2, p_x3);

    // #9-10: router
    zero_cnt_kernel<<<1, 64>>>(p_cnt);
    router_kernel<<<TT, 256>>>(p_x3, gw, p_cnt, p_tok, p_wgt, p_inv);

    // #11: MoE gate_up (v15)
    dim3 ggu(DFF / 64, 8, NE);
    moe_gate_up_v15<<<ggu, 256, V15_DSMEM>>>(p_x3, guw, p_cnt, p_tok, p_wgt, p_act);

    // #12: MoE down (v15)
    dim3 gdn(DD / 128, 8, NE);
    moe_down_v15<<<gdn, 256, V15_DSMEM>>>(p_act, dw, p_cnt, p_part);

    // #13: gather partials into out
    gather_kernel<<<TT, 256>>>(p_part, p_inv, out);
}